// round 1
// baseline (speedup 1.0000x reference)
#include <cuda_runtime.h>
#include <cuda_bf16.h>
#include <mma.h>

using namespace nvcuda;

// Problem constants
constexpr int NB = 4;        // batch
constexpr int SL = 2048;     // query seq len
constexpr int TL = 2048;     // kv seq len
constexpr int DM = 512;      // model dim
constexpr int NH = 8;        // heads
constexpr int DH = 64;       // dim per head
constexpr int MROWS = NB * SL;  // 8192

// Scratch (allocation-free rule: __device__ globals)
__device__ float g_Q[NB * SL * DM];
__device__ float g_K[NB * TL * DM];
__device__ float g_V[NB * TL * DM];
__device__ float g_Y[NB * SL * DM];

// ---------------------------------------------------------------------------
// GEMM: C[M,Nc] = A[M,K] @ W[Nc,K]^T + bias,  tf32 wmma, tile 64x64x32
// ---------------------------------------------------------------------------
constexpr int BM = 64, BN = 64, BK = 32;
constexpr int LDA = BK + 4;   // 36, mult of 4
constexpr int LDC = 68;       // 64 + 4

__global__ __launch_bounds__(128) void gemm_xwT(
    const float* __restrict__ A, const float* __restrict__ W,
    const float* __restrict__ bias, float* __restrict__ C,
    int M, int K, int Ncols)
{
    __shared__ __align__(16) float Ash[BM * LDA];
    __shared__ __align__(16) float Bsh[BN * LDA];
    __shared__ __align__(16) float Csh[BM * LDC];

    const int m0 = blockIdx.y * BM;
    const int n0 = blockIdx.x * BN;
    const int tid = threadIdx.x;
    const int warp = tid >> 5;
    const int wy = warp >> 1;   // 0..1
    const int wx = warp & 1;    // 0..1

    wmma::fragment<wmma::accumulator, 16, 16, 8, float> acc[2][2];
#pragma unroll
    for (int i = 0; i < 2; i++)
#pragma unroll
        for (int j = 0; j < 2; j++) wmma::fill_fragment(acc[i][j], 0.0f);

    for (int k0 = 0; k0 < K; k0 += BK) {
#pragma unroll
        for (int i = 0; i < 4; i++) {
            int lin = tid + i * 128;        // 512 float4 per tile
            int r = lin >> 3;               // 8 float4 per row
            int c4 = lin & 7;
            float4 va = *(const float4*)(A + (size_t)(m0 + r) * K + k0 + c4 * 4);
            *(float4*)(Ash + r * LDA + c4 * 4) = va;
            float4 vb = *(const float4*)(W + (size_t)(n0 + r) * K + k0 + c4 * 4);
            *(float4*)(Bsh + r * LDA + c4 * 4) = vb;
        }
        __syncthreads();

#pragma unroll
        for (int kk = 0; kk < BK; kk += 8) {
            wmma::fragment<wmma::matrix_a, 16, 16, 8, wmma::precision::tf32, wmma::row_major> af[2];
            wmma::fragment<wmma::matrix_b, 16, 16, 8, wmma::precision::tf32, wmma::col_major> bf[2];
#pragma unroll
            for (int i = 0; i < 2; i++) {
                wmma::load_matrix_sync(af[i], Ash + (wy * 32 + i * 16) * LDA + kk, LDA);
#pragma unroll
                for (int e = 0; e < af[i].num_elements; e++)
                    af[i].x[e] = wmma::__float_to_tf32(af[i].x[e]);
                wmma::load_matrix_sync(bf[i], Bsh + (wx * 32 + i * 16) * LDA + kk, LDA);
#pragma unroll
                for (int e = 0; e < bf[i].num_elements; e++)
                    bf[i].x[e] = wmma::__float_to_tf32(bf[i].x[e]);
            }
#pragma unroll
            for (int i = 0; i < 2; i++)
#pragma unroll
                for (int j = 0; j < 2; j++)
                    wmma::mma_sync(acc[i][j], af[i], bf[j], acc[i][j]);
        }
        __syncthreads();
    }

#pragma unroll
    for (int i = 0; i < 2; i++)
#pragma unroll
        for (int j = 0; j < 2; j++)
            wmma::store_matrix_sync(Csh + (wy * 32 + i * 16) * LDC + wx * 32 + j * 16,
                                    acc[i][j], LDC, wmma::mem_row_major);
    __syncthreads();

#pragma unroll
    for (int i = 0; i < 8; i++) {
        int lin = tid + i * 128;    // 1024 float4
        int r = lin >> 4;
        int c4 = lin & 15;
        float4 v = *(float4*)(Csh + r * LDC + c4 * 4);
        int n = n0 + c4 * 4;
        float4 b4 = *(const float4*)(bias + n);
        v.x += b4.x; v.y += b4.y; v.z += b4.z; v.w += b4.w;
        *(float4*)(C + (size_t)(m0 + r) * Ncols + n) = v;
    }
}

// ---------------------------------------------------------------------------
// Fused flash attention: one block = 64 query rows of one (batch, head).
// Q frags in registers; K/V chunks (64 tokens) in shared; online softmax;
// O accumulated in shared via wmma load/mma/store.
// ---------------------------------------------------------------------------
constexpr int ALD = 68;  // 64 + 4 pad

__global__ __launch_bounds__(256) void attn_kernel(
    const float* __restrict__ Q, const float* __restrict__ K,
    const float* __restrict__ V, float* __restrict__ Y)
{
    extern __shared__ __align__(16) float sm[];
    float* Ksh = sm;                 // 64*68
    float* Vsh = Ksh + 64 * ALD;     // 64*68
    float* Ssh = Vsh + 64 * ALD;     // 64*68 (also Q staging)
    float* Osh = Ssh + 64 * ALD;     // 64*68
    float* msh = Osh + 64 * ALD;     // 64
    float* lsh = msh + 64;           // 64

    const int s0 = blockIdx.x * 64;
    const int h = blockIdx.y;
    const int n = blockIdx.z;
    const int tid = threadIdx.x;
    const int warp = tid >> 5;
    const int wy = warp >> 1;   // 0..3 -> 16-row strip
    const int wx = warp & 1;    // 0..1 -> 32-col strip

    const size_t baseQ = ((size_t)n * SL) * DM + (size_t)h * DH;
    const size_t baseK = ((size_t)n * TL) * DM + (size_t)h * DH;

    // Stage Q tile into Ssh, init O/m/l
#pragma unroll
    for (int i = 0; i < 4; i++) {
        int lin = tid + i * 256;   // 1024 float4
        int r = lin >> 4, c4 = lin & 15;
        *(float4*)(Ssh + r * ALD + c4 * 4) =
            *(const float4*)(Q + baseQ + (size_t)(s0 + r) * DM + c4 * 4);
        float4 z = make_float4(0.f, 0.f, 0.f, 0.f);
        *(float4*)(Osh + r * ALD + c4 * 4) = z;
    }
    if (tid < 64) { msh[tid] = -1e30f; lsh[tid] = 0.0f; }
    __syncthreads();

    // Q fragments resident for the whole kernel (rows wy*16, 8 k-steps over DH)
    wmma::fragment<wmma::matrix_a, 16, 16, 8, wmma::precision::tf32, wmma::row_major> qf[8];
#pragma unroll
    for (int kk = 0; kk < 8; kk++) {
        wmma::load_matrix_sync(qf[kk], Ssh + (wy * 16) * ALD + kk * 8, ALD);
#pragma unroll
        for (int e = 0; e < qf[kk].num_elements; e++)
            qf[kk].x[e] = wmma::__float_to_tf32(qf[kk].x[e]);
    }
    __syncthreads();   // Ssh free for score tiles now

    const float scale = 0.125f;  // 1/sqrt(64)

    for (int t0 = 0; t0 < TL; t0 += 64) {
        // Load K/V chunk
#pragma unroll
        for (int i = 0; i < 4; i++) {
            int lin = tid + i * 256;
            int r = lin >> 4, c4 = lin & 15;
            size_t off = baseK + (size_t)(t0 + r) * DM + c4 * 4;
            *(float4*)(Ksh + r * ALD + c4 * 4) = *(const float4*)(K + off);
            *(float4*)(Vsh + r * ALD + c4 * 4) = *(const float4*)(V + off);
        }
        __syncthreads();

        // S = scale * Q K^T  (K chunk is [t,d] row-major == col-major (d,t))
        wmma::fragment<wmma::accumulator, 16, 16, 8, float> sacc[2];
        wmma::fill_fragment(sacc[0], 0.0f);
        wmma::fill_fragment(sacc[1], 0.0f);
#pragma unroll
        for (int kk = 0; kk < 8; kk++) {
#pragma unroll
            for (int j = 0; j < 2; j++) {
                wmma::fragment<wmma::matrix_b, 16, 16, 8, wmma::precision::tf32, wmma::col_major> kb;
                wmma::load_matrix_sync(kb, Ksh + (wx * 32 + j * 16) * ALD + kk * 8, ALD);
#pragma unroll
                for (int e = 0; e < kb.num_elements; e++)
                    kb.x[e] = wmma::__float_to_tf32(kb.x[e]);
                wmma::mma_sync(sacc[j], qf[kk], kb, sacc[j]);
            }
        }
#pragma unroll
        for (int j = 0; j < 2; j++) {
#pragma unroll
            for (int e = 0; e < sacc[j].num_elements; e++) sacc[j].x[e] *= scale;
            wmma::store_matrix_sync(Ssh + (wy * 16) * ALD + wx * 32 + j * 16,
                                    sacc[j], ALD, wmma::mem_row_major);
        }
        __syncthreads();

        // Online softmax: 4 threads per row, 16 cols each
        {
            const int r = tid >> 2, q = tid & 3;
            float* srow = Ssh + r * ALD + q * 16;
            float* orow = Osh + r * ALD + q * 16;
            float m_old = msh[r];
            float l_old = lsh[r];
            __syncwarp();
            float vmax = srow[0];
#pragma unroll
            for (int c = 1; c < 16; c++) vmax = fmaxf(vmax, srow[c]);
            vmax = fmaxf(vmax, __shfl_xor_sync(0xffffffffu, vmax, 1));
            vmax = fmaxf(vmax, __shfl_xor_sync(0xffffffffu, vmax, 2));
            float m_new = fmaxf(m_old, vmax);
            float psum = 0.0f;
#pragma unroll
            for (int c = 0; c < 16; c++) {
                float p = __expf(srow[c] - m_new);
                srow[c] = p;
                psum += p;
            }
            psum += __shfl_xor_sync(0xffffffffu, psum, 1);
            psum += __shfl_xor_sync(0xffffffffu, psum, 2);
            float alpha = __expf(m_old - m_new);
#pragma unroll
            for (int c = 0; c < 16; c++) orow[c] *= alpha;
            if (q == 0) { msh[r] = m_new; lsh[r] = alpha * l_old + psum; }
        }
        __syncthreads();

        // O += P V
        wmma::fragment<wmma::accumulator, 16, 16, 8, float> oacc[2];
#pragma unroll
        for (int j = 0; j < 2; j++)
            wmma::load_matrix_sync(oacc[j], Osh + (wy * 16) * ALD + wx * 32 + j * 16,
                                   ALD, wmma::mem_row_major);
#pragma unroll
        for (int kk = 0; kk < 8; kk++) {
            wmma::fragment<wmma::matrix_a, 16, 16, 8, wmma::precision::tf32, wmma::row_major> pa;
            wmma::load_matrix_sync(pa, Ssh + (wy * 16) * ALD + kk * 8, ALD);
#pragma unroll
            for (int e = 0; e < pa.num_elements; e++)
                pa.x[e] = wmma::__float_to_tf32(pa.x[e]);
#pragma unroll
            for (int j = 0; j < 2; j++) {
                wmma::fragment<wmma::matrix_b, 16, 16, 8, wmma::precision::tf32, wmma::row_major> vb;
                wmma::load_matrix_sync(vb, Vsh + (kk * 8) * ALD + wx * 32 + j * 16, ALD);
#pragma unroll
                for (int e = 0; e < vb.num_elements; e++)
                    vb.x[e] = wmma::__float_to_tf32(vb.x[e]);
                wmma::mma_sync(oacc[j], pa, vb, oacc[j]);
            }
        }
#pragma unroll
        for (int j = 0; j < 2; j++)
            wmma::store_matrix_sync(Osh + (wy * 16) * ALD + wx * 32 + j * 16,
                                    oacc[j], ALD, wmma::mem_row_major);
        __syncthreads();
    }

    // Finalize: Y[n, s0+r, h*64+c] = O[r][c] / l[r]
#pragma unroll
    for (int i = 0; i < 4; i++) {
        int lin = tid + i * 256;
        int r = lin >> 4, c4 = lin & 15;
        float inv = 1.0f / lsh[r];
        float4 v = *(float4*)(Osh + r * ALD + c4 * 4);
        v.x *= inv; v.y *= inv; v.z *= inv; v.w *= inv;
        *(float4*)(Y + baseQ + (size_t)(s0 + r) * DM + c4 * 4) = v;
    }
}

// ---------------------------------------------------------------------------
// Launch
// ---------------------------------------------------------------------------
extern "C" void kernel_launch(void* const* d_in, const int* in_sizes, int n_in,
                              void* d_out, int out_size)
{
    (void)in_sizes; (void)n_in; (void)out_size;
    const float* query = (const float*)d_in[0];
    const float* key   = (const float*)d_in[1];
    const float* value = (const float*)d_in[2];
    const float* Wq = (const float*)d_in[3];
    const float* bq = (const float*)d_in[4];
    const float* Wk = (const float*)d_in[5];
    const float* bk = (const float*)d_in[6];
    const float* Wv = (const float*)d_in[7];
    const float* bv = (const float*)d_in[8];
    const float* Wo = (const float*)d_in[9];
    const float* bo = (const float*)d_in[10];
    float* out = (float*)d_out;

    float *gq, *gk, *gv, *gy;
    cudaGetSymbolAddress((void**)&gq, g_Q);
    cudaGetSymbolAddress((void**)&gk, g_K);
    cudaGetSymbolAddress((void**)&gv, g_V);
    cudaGetSymbolAddress((void**)&gy, g_Y);

    dim3 ggrid(DM / BN, MROWS / BM);   // (8, 128)
    gemm_xwT<<<ggrid, 128>>>(query, Wq, bq, gq, MROWS, DM, DM);
    gemm_xwT<<<ggrid, 128>>>(key,   Wk, bk, gk, MROWS, DM, DM);
    gemm_xwT<<<ggrid, 128>>>(value, Wv, bv, gv, MROWS, DM, DM);

    const int smem = (4 * 64 * ALD + 128) * (int)sizeof(float);  // ~70.6 KB
    static int attr_set = 0;
    // Setting a func attribute is idempotent and capture-safe; do it every call.
    cudaFuncSetAttribute(attn_kernel, cudaFuncAttributeMaxDynamicSharedMemorySize, smem);
    (void)attr_set;

    dim3 agrid(SL / 64, NH, NB);       // (32, 8, 4)
    attn_kernel<<<agrid, 256, smem>>>(gq, gk, gv, gy);

    gemm_xwT<<<ggrid, 128>>>(gy, Wo, bo, out, MROWS, DM, DM);
}

// round 3
// speedup vs baseline: 1.7258x; 1.7258x over previous
#include <cstdint>
#include <cstddef>
#include <cuda_runtime.h>
#include <cuda_bf16.h>
#include <mma.h>

using namespace nvcuda;

// Problem constants
constexpr int NB = 4;        // batch
constexpr int SL = 2048;     // query seq len
constexpr int TL = 2048;     // kv seq len
constexpr int DM = 512;      // model dim
constexpr int NH = 8;        // heads
constexpr int DH = 64;       // dim per head
constexpr int MROWS = NB * SL;  // 8192

// Scratch (allocation-free rule: __device__ globals)
__device__ float g_Q[NB * SL * DM];
__device__ float g_K[NB * TL * DM];
__device__ float g_V[NB * TL * DM];
__device__ float g_Y[NB * SL * DM];

// ---------------------------------------------------------------------------
// Helpers
// ---------------------------------------------------------------------------
__device__ __forceinline__ unsigned f2tf32(float f) {
    unsigned u;
    asm("cvt.rna.tf32.f32 %0, %1;" : "=r"(u) : "f"(f));
    return u;
}
__device__ __forceinline__ float tf32r(float f) {
    return __uint_as_float(f2tf32(f));
}
__device__ __forceinline__ float ex2f(float x) {
    float y;
    asm("ex2.approx.f32 %0, %1;" : "=f"(y) : "f"(x));
    return y;
}
__device__ __forceinline__ void mma_16n8k8(
    float& d0, float& d1, float& d2, float& d3,
    unsigned a0, unsigned a1, unsigned a2, unsigned a3,
    unsigned b0, unsigned b1)
{
    asm volatile(
        "mma.sync.aligned.m16n8k8.row.col.f32.tf32.tf32.f32 "
        "{%0,%1,%2,%3}, {%4,%5,%6,%7}, {%8,%9}, {%0,%1,%2,%3};"
        : "+f"(d0), "+f"(d1), "+f"(d2), "+f"(d3)
        : "r"(a0), "r"(a1), "r"(a2), "r"(a3), "r"(b0), "r"(b1));
}
__device__ __forceinline__ void cp_async16(void* smem_dst, const void* gptr) {
    unsigned dst = (unsigned)__cvta_generic_to_shared(smem_dst);
    asm volatile("cp.async.cg.shared.global [%0], [%1], 16;" :: "r"(dst), "l"(gptr));
}
__device__ __forceinline__ void cp_async_commit() {
    asm volatile("cp.async.commit_group;");
}
__device__ __forceinline__ void cp_async_wait_all() {
    asm volatile("cp.async.wait_group 0;");
}

// ---------------------------------------------------------------------------
// GEMM: C[M,Nc] = A[M,K] @ W[Nc,K]^T + bias,  tf32 wmma, tile 64x64x32
// round_flag: round outputs to tf32 (so downstream kernels skip per-load cvt)
// ---------------------------------------------------------------------------
constexpr int BM = 64, BN = 64, BK = 32;
constexpr int LDA = BK + 4;   // 36
constexpr int LDC = 68;       // 64 + 4

__global__ __launch_bounds__(128) void gemm_xwT(
    const float* __restrict__ A, const float* __restrict__ W,
    const float* __restrict__ bias, float* __restrict__ C,
    int M, int K, int Ncols, int round_flag)
{
    __shared__ __align__(16) float Ash[BM * LDA];
    __shared__ __align__(16) float Bsh[BN * LDA];
    __shared__ __align__(16) float Csh[BM * LDC];

    const int m0 = blockIdx.y * BM;
    const int n0 = blockIdx.x * BN;
    const int tid = threadIdx.x;
    const int warp = tid >> 5;
    const int wy = warp >> 1;
    const int wx = warp & 1;

    wmma::fragment<wmma::accumulator, 16, 16, 8, float> acc[2][2];
#pragma unroll
    for (int i = 0; i < 2; i++)
#pragma unroll
        for (int j = 0; j < 2; j++) wmma::fill_fragment(acc[i][j], 0.0f);

    for (int k0 = 0; k0 < K; k0 += BK) {
#pragma unroll
        for (int i = 0; i < 4; i++) {
            int lin = tid + i * 128;
            int r = lin >> 3;
            int c4 = lin & 7;
            float4 va = *(const float4*)(A + (size_t)(m0 + r) * K + k0 + c4 * 4);
            *(float4*)(Ash + r * LDA + c4 * 4) = va;
            float4 vb = *(const float4*)(W + (size_t)(n0 + r) * K + k0 + c4 * 4);
            *(float4*)(Bsh + r * LDA + c4 * 4) = vb;
        }
        __syncthreads();

#pragma unroll
        for (int kk = 0; kk < BK; kk += 8) {
            wmma::fragment<wmma::matrix_a, 16, 16, 8, wmma::precision::tf32, wmma::row_major> af[2];
            wmma::fragment<wmma::matrix_b, 16, 16, 8, wmma::precision::tf32, wmma::col_major> bf[2];
#pragma unroll
            for (int i = 0; i < 2; i++) {
                wmma::load_matrix_sync(af[i], Ash + (wy * 32 + i * 16) * LDA + kk, LDA);
#pragma unroll
                for (int e = 0; e < af[i].num_elements; e++)
                    af[i].x[e] = wmma::__float_to_tf32(af[i].x[e]);
                wmma::load_matrix_sync(bf[i], Bsh + (wx * 32 + i * 16) * LDA + kk, LDA);
#pragma unroll
                for (int e = 0; e < bf[i].num_elements; e++)
                    bf[i].x[e] = wmma::__float_to_tf32(bf[i].x[e]);
            }
#pragma unroll
            for (int i = 0; i < 2; i++)
#pragma unroll
                for (int j = 0; j < 2; j++)
                    wmma::mma_sync(acc[i][j], af[i], bf[j], acc[i][j]);
        }
        __syncthreads();
    }

#pragma unroll
    for (int i = 0; i < 2; i++)
#pragma unroll
        for (int j = 0; j < 2; j++)
            wmma::store_matrix_sync(Csh + (wy * 32 + i * 16) * LDC + wx * 32 + j * 16,
                                    acc[i][j], LDC, wmma::mem_row_major);
    __syncthreads();

#pragma unroll
    for (int i = 0; i < 8; i++) {
        int lin = tid + i * 128;
        int r = lin >> 4;
        int c4 = lin & 15;
        float4 v = *(float4*)(Csh + r * LDC + c4 * 4);
        int n = n0 + c4 * 4;
        float4 b4 = *(const float4*)(bias + n);
        v.x += b4.x; v.y += b4.y; v.z += b4.z; v.w += b4.w;
        if (round_flag) {
            v.x = tf32r(v.x); v.y = tf32r(v.y);
            v.z = tf32r(v.z); v.w = tf32r(v.w);
        }
        *(float4*)(C + (size_t)(m0 + r) * Ncols + n) = v;
    }
}

// ---------------------------------------------------------------------------
// Flash attention v2: raw mma.m16n8k8 tf32, register-resident S/P/O/softmax.
// Block = 128 threads (4 warps), Br=64 rows (16/warp), Bc=64 K/V chunks.
// K/V double-buffered in shared via cp.async; ONE __syncthreads per chunk.
// K/V are pre-rounded to tf32 by the projection epilogue (no cvt here).
// Softmax in log2 domain: scale = 0.125 * log2(e) folded into Q.
// ---------------------------------------------------------------------------
constexpr int ALD = 68;                 // 64 + 4 pad (floats)
constexpr int TSTRIDE = 64 * ALD;       // one K or V tile (floats)
constexpr int SSTRIDE = 2 * TSTRIDE;    // one stage = K + V
constexpr int ATTN_SMEM = 2 * SSTRIDE * (int)sizeof(float);  // 69632 B

__global__ __launch_bounds__(128) void attn2_kernel(
    const float* __restrict__ Q, const float* __restrict__ K,
    const float* __restrict__ V, float* __restrict__ Y)
{
    extern __shared__ __align__(16) float sm[];

    const int tid = threadIdx.x;
    const int lane = tid & 31;
    const int w = tid >> 5;
    const int q = lane & 3;        // thread-in-quad
    const int gr = lane >> 2;      // quad index = row-in-8
    const int s0 = blockIdx.x * 64;
    const int h = blockIdx.y;
    const int n = blockIdx.z;

    const float* Qg = Q + (size_t)n * SL * DM + (size_t)h * DH;
    const float* Kg = K + (size_t)n * TL * DM + (size_t)h * DH;
    const float* Vg = V + (size_t)n * TL * DM + (size_t)h * DH;
    float* Yg       = Y + (size_t)n * SL * DM + (size_t)h * DH;

    // ---- Q fragments (resident), scaled by 0.125*log2(e), tf32-rounded ----
    const float SCALE = 0.125f * 1.4426950408889634f;
    const int r_lo = s0 + w * 16 + gr;   // rows r_lo and r_lo+8
    unsigned qa[8][4];
#pragma unroll
    for (int kt = 0; kt < 8; kt++) {
        int d0 = kt * 8;
        qa[kt][0] = f2tf32(Qg[(size_t)r_lo * DM + d0 + q] * SCALE);
        qa[kt][1] = f2tf32(Qg[(size_t)(r_lo + 8) * DM + d0 + q] * SCALE);
        qa[kt][2] = f2tf32(Qg[(size_t)r_lo * DM + d0 + 4 + q] * SCALE);
        qa[kt][3] = f2tf32(Qg[(size_t)(r_lo + 8) * DM + d0 + 4 + q] * SCALE);
    }

    float o[8][4];
#pragma unroll
    for (int j = 0; j < 8; j++)
#pragma unroll
        for (int e = 0; e < 4; e++) o[j][e] = 0.0f;

    float m_lo = -1e30f, m_hi = -1e30f, l_lo = 0.0f, l_hi = 0.0f;

    // ---- chunk loader: 16 cp.async(16B) per thread ----
    auto load_chunk = [&](int t0, int stage) {
        float* Ksh = sm + stage * SSTRIDE;
        float* Vsh = Ksh + TSTRIDE;
#pragma unroll
        for (int i = 0; i < 8; i++) {
            int lin = tid + i * 128;        // 0..1023
            int r = lin >> 4, c4 = lin & 15;
            size_t goff = (size_t)(t0 + r) * DM + c4 * 4;
            cp_async16(Ksh + r * ALD + c4 * 4, Kg + goff);
            cp_async16(Vsh + r * ALD + c4 * 4, Vg + goff);
        }
        cp_async_commit();
    };

    load_chunk(0, 0);

    const int NCHUNK = TL / 64;   // 32
    for (int c = 0; c < NCHUNK; c++) {
        float* Ksh = sm + (c & 1) * SSTRIDE;
        float* Vsh = Ksh + TSTRIDE;

        cp_async_wait_all();
        __syncthreads();

        if (c + 1 < NCHUNK) load_chunk((c + 1) * 64, (c + 1) & 1);

        // ---- S = Q K^T  (16 x 64 per warp, log2-domain scores) ----
        float s[8][4];
#pragma unroll
        for (int j = 0; j < 8; j++)
#pragma unroll
            for (int e = 0; e < 4; e++) s[j][e] = 0.0f;

        const float* Kb = Ksh + gr * ALD + q;   // + j*8*ALD + kt*8 (+4)
#pragma unroll
        for (int kt = 0; kt < 8; kt++) {
#pragma unroll
            for (int j = 0; j < 8; j++) {
                const float* p = Kb + j * (8 * ALD) + kt * 8;
                unsigned b0 = __float_as_uint(p[0]);
                unsigned b1 = __float_as_uint(p[4]);
                mma_16n8k8(s[j][0], s[j][1], s[j][2], s[j][3],
                           qa[kt][0], qa[kt][1], qa[kt][2], qa[kt][3], b0, b1);
            }
        }

        // ---- online softmax (registers + quad shuffles only) ----
        float mc_lo = -1e30f, mc_hi = -1e30f;
#pragma unroll
        for (int j = 0; j < 8; j++) {
            mc_lo = fmaxf(mc_lo, fmaxf(s[j][0], s[j][1]));
            mc_hi = fmaxf(mc_hi, fmaxf(s[j][2], s[j][3]));
        }
        mc_lo = fmaxf(mc_lo, __shfl_xor_sync(0xffffffffu, mc_lo, 1));
        mc_lo = fmaxf(mc_lo, __shfl_xor_sync(0xffffffffu, mc_lo, 2));
        mc_hi = fmaxf(mc_hi, __shfl_xor_sync(0xffffffffu, mc_hi, 1));
        mc_hi = fmaxf(mc_hi, __shfl_xor_sync(0xffffffffu, mc_hi, 2));

        float mn_lo = fmaxf(m_lo, mc_lo);
        float mn_hi = fmaxf(m_hi, mc_hi);
        float al = ex2f(m_lo - mn_lo);
        float ah = ex2f(m_hi - mn_hi);

        float sl = 0.0f, sh = 0.0f;
#pragma unroll
        for (int j = 0; j < 8; j++) {
            float p0 = ex2f(s[j][0] - mn_lo);
            float p1 = ex2f(s[j][1] - mn_lo);
            float p2 = ex2f(s[j][2] - mn_hi);
            float p3 = ex2f(s[j][3] - mn_hi);
            sl += p0 + p1;
            sh += p2 + p3;
            // store as tf32-rounded bits (P is the next A operand)
            s[j][0] = __uint_as_float(f2tf32(p0));
            s[j][1] = __uint_as_float(f2tf32(p1));
            s[j][2] = __uint_as_float(f2tf32(p2));
            s[j][3] = __uint_as_float(f2tf32(p3));
        }
        sl += __shfl_xor_sync(0xffffffffu, sl, 1);
        sl += __shfl_xor_sync(0xffffffffu, sl, 2);
        sh += __shfl_xor_sync(0xffffffffu, sh, 1);
        sh += __shfl_xor_sync(0xffffffffu, sh, 2);

        l_lo = l_lo * al + sl;
        l_hi = l_hi * ah + sh;
        m_lo = mn_lo;
        m_hi = mn_hi;

#pragma unroll
        for (int j = 0; j < 8; j++) {
            o[j][0] *= al; o[j][1] *= al;
            o[j][2] *= ah; o[j][3] *= ah;
        }

        // ---- O += P V : convert C-layout P to A-layout via quad shuffles ----
        const int srcA = (lane & ~3) + (q >> 1);
        const int srcB = srcA + 2;
        const float* Vb = Vsh + q * ALD + gr;  // + kt*8*ALD + j*8 (+4*ALD)
#pragma unroll
        for (int kt = 0; kt < 8; kt++) {
            float x0 = __shfl_sync(0xffffffffu, s[kt][0], srcA);
            float x1 = __shfl_sync(0xffffffffu, s[kt][1], srcA);
            float y0 = __shfl_sync(0xffffffffu, s[kt][0], srcB);
            float y1 = __shfl_sync(0xffffffffu, s[kt][1], srcB);
            float z0 = __shfl_sync(0xffffffffu, s[kt][2], srcA);
            float z1 = __shfl_sync(0xffffffffu, s[kt][3], srcA);
            float w0 = __shfl_sync(0xffffffffu, s[kt][2], srcB);
            float w1 = __shfl_sync(0xffffffffu, s[kt][3], srcB);
            unsigned a0 = __float_as_uint((q & 1) ? x1 : x0);  // (r_lo, k=q)
            unsigned a1 = __float_as_uint((q & 1) ? z1 : z0);  // (r_hi, k=q)
            unsigned a2 = __float_as_uint((q & 1) ? y1 : y0);  // (r_lo, k=q+4)
            unsigned a3 = __float_as_uint((q & 1) ? w1 : w0);  // (r_hi, k=q+4)
#pragma unroll
            for (int j = 0; j < 8; j++) {
                const float* p = Vb + kt * (8 * ALD) + j * 8;
                unsigned b0 = __float_as_uint(p[0]);
                unsigned b1 = __float_as_uint(p[4 * ALD]);
                mma_16n8k8(o[j][0], o[j][1], o[j][2], o[j][3],
                           a0, a1, a2, a3, b0, b1);
            }
        }
    }

    // ---- epilogue: divide by l, write float2 pairs ----
    float il_lo = 1.0f / l_lo;
    float il_hi = 1.0f / l_hi;
#pragma unroll
    for (int j = 0; j < 8; j++) {
        int col = 8 * j + 2 * q;
        float2 v0 = make_float2(o[j][0] * il_lo, o[j][1] * il_lo);
        *(float2*)(Yg + (size_t)r_lo * DM + col) = v0;
        float2 v1 = make_float2(o[j][2] * il_hi, o[j][3] * il_hi);
        *(float2*)(Yg + (size_t)(r_lo + 8) * DM + col) = v1;
    }
}

// ---------------------------------------------------------------------------
// Launch
// ---------------------------------------------------------------------------
extern "C" void kernel_launch(void* const* d_in, const int* in_sizes, int n_in,
                              void* d_out, int out_size)
{
    (void)in_sizes; (void)n_in; (void)out_size;
    const float* query = (const float*)d_in[0];
    const float* key   = (const float*)d_in[1];
    const float* value = (const float*)d_in[2];
    const float* Wq = (const float*)d_in[3];
    const float* bq = (const float*)d_in[4];
    const float* Wk = (const float*)d_in[5];
    const float* bk = (const float*)d_in[6];
    const float* Wv = (const float*)d_in[7];
    const float* bv = (const float*)d_in[8];
    const float* Wo = (const float*)d_in[9];
    const float* bo = (const float*)d_in[10];
    float* out = (float*)d_out;

    float *gq, *gk, *gv, *gy;
    cudaGetSymbolAddress((void**)&gq, g_Q);
    cudaGetSymbolAddress((void**)&gk, g_K);
    cudaGetSymbolAddress((void**)&gv, g_V);
    cudaGetSymbolAddress((void**)&gy, g_Y);

    dim3 ggrid(DM / BN, MROWS / BM);   // (8, 128)
    // Q: not pre-rounded (attention rescales + rounds Q itself).
    gemm_xwT<<<ggrid, 128>>>(query, Wq, bq, gq, MROWS, DM, DM, 0);
    // K/V: round to tf32 so attention smem fragments need no cvt.
    gemm_xwT<<<ggrid, 128>>>(key,   Wk, bk, gk, MROWS, DM, DM, 1);
    gemm_xwT<<<ggrid, 128>>>(value, Wv, bv, gv, MROWS, DM, DM, 1);

    cudaFuncSetAttribute(attn2_kernel, cudaFuncAttributeMaxDynamicSharedMemorySize,
                         ATTN_SMEM);
    dim3 agrid(SL / 64, NH, NB);       // (32, 8, 4)
    attn2_kernel<<<agrid, 128, ATTN_SMEM>>>(gq, gk, gv, gy);

    gemm_xwT<<<ggrid, 128>>>(gy, Wo, bo, out, MROWS, DM, DM, 0);
}

// round 4
// speedup vs baseline: 2.0816x; 1.2062x over previous
#include <cstdint>
#include <cstddef>
#include <cuda_runtime.h>
#include <cuda_bf16.h>
#include <mma.h>

using namespace nvcuda;

// Problem constants
constexpr int NB = 4;        // batch
constexpr int SL = 2048;     // query seq len
constexpr int TL = 2048;     // kv seq len
constexpr int DM = 512;      // model dim
constexpr int NH = 8;        // heads
constexpr int DH = 64;       // dim per head
constexpr int MROWS = NB * SL;  // 8192

// Scratch (allocation-free rule: __device__ globals)
__device__ float g_Q[NB * SL * DM];
__device__ float g_K[NB * TL * DM];
__device__ float g_VT[NB * NH * DH * TL];   // V transposed per head: [n][h][d][t]
__device__ float g_Y[NB * SL * DM];

// ---------------------------------------------------------------------------
// Helpers
// ---------------------------------------------------------------------------
__device__ __forceinline__ unsigned f2tf32(float f) {
    unsigned u;
    asm("cvt.rna.tf32.f32 %0, %1;" : "=r"(u) : "f"(f));
    return u;
}
__device__ __forceinline__ float tf32r(float f) {
    return __uint_as_float(f2tf32(f));
}
__device__ __forceinline__ float ex2f(float x) {
    float y;
    asm("ex2.approx.f32 %0, %1;" : "=f"(y) : "f"(x));
    return y;
}
__device__ __forceinline__ void mma_16n8k8(
    float& d0, float& d1, float& d2, float& d3,
    unsigned a0, unsigned a1, unsigned a2, unsigned a3,
    unsigned b0, unsigned b1)
{
    asm volatile(
        "mma.sync.aligned.m16n8k8.row.col.f32.tf32.tf32.f32 "
        "{%0,%1,%2,%3}, {%4,%5,%6,%7}, {%8,%9}, {%0,%1,%2,%3};"
        : "+f"(d0), "+f"(d1), "+f"(d2), "+f"(d3)
        : "r"(a0), "r"(a1), "r"(a2), "r"(a3), "r"(b0), "r"(b1));
}
__device__ __forceinline__ void cp_async16(void* smem_dst, const void* gptr) {
    unsigned dst = (unsigned)__cvta_generic_to_shared(smem_dst);
    asm volatile("cp.async.cg.shared.global [%0], [%1], 16;" :: "r"(dst), "l"(gptr));
}
__device__ __forceinline__ void cp_async_commit() {
    asm volatile("cp.async.commit_group;");
}
__device__ __forceinline__ void cp_async_wait_all() {
    asm volatile("cp.async.wait_group 0;");
}

// ---------------------------------------------------------------------------
// GEMM: C[M,Nc] = A[M,K] @ W[Nc,K]^T + bias, tf32 wmma, tile 64x64x32.
// mode 0: plain fp32 out.  mode 1: out rounded to tf32.
// mode 2: out rounded to tf32 AND stored transposed per head into
//         VT[((b*NH+h)*DH + d)*TL + t]  (b from m0, h from n0).
// tf32 rounding of A/W applied once at smem-store time (not per fragment).
// ---------------------------------------------------------------------------
constexpr int BM = 64, BN = 64, BK = 32;
constexpr int LDA = BK + 4;   // 36
constexpr int LDC = 68;       // 64 + 4

__global__ __launch_bounds__(128) void gemm_xwT(
    const float* __restrict__ A, const float* __restrict__ W,
    const float* __restrict__ bias, float* __restrict__ C,
    int M, int K, int Ncols, int mode)
{
    __shared__ __align__(16) float Ash[BM * LDA];
    __shared__ __align__(16) float Bsh[BN * LDA];
    __shared__ __align__(16) float Csh[BM * LDC];

    const int m0 = blockIdx.y * BM;
    const int n0 = blockIdx.x * BN;
    const int tid = threadIdx.x;
    const int warp = tid >> 5;
    const int wy = warp >> 1;
    const int wx = warp & 1;

    wmma::fragment<wmma::accumulator, 16, 16, 8, float> acc[2][2];
#pragma unroll
    for (int i = 0; i < 2; i++)
#pragma unroll
        for (int j = 0; j < 2; j++) wmma::fill_fragment(acc[i][j], 0.0f);

    for (int k0 = 0; k0 < K; k0 += BK) {
#pragma unroll
        for (int i = 0; i < 4; i++) {
            int lin = tid + i * 128;
            int r = lin >> 3;
            int c4 = lin & 7;
            float4 va = *(const float4*)(A + (size_t)(m0 + r) * K + k0 + c4 * 4);
            va.x = tf32r(va.x); va.y = tf32r(va.y);
            va.z = tf32r(va.z); va.w = tf32r(va.w);
            *(float4*)(Ash + r * LDA + c4 * 4) = va;
            float4 vb = *(const float4*)(W + (size_t)(n0 + r) * K + k0 + c4 * 4);
            vb.x = tf32r(vb.x); vb.y = tf32r(vb.y);
            vb.z = tf32r(vb.z); vb.w = tf32r(vb.w);
            *(float4*)(Bsh + r * LDA + c4 * 4) = vb;
        }
        __syncthreads();

#pragma unroll
        for (int kk = 0; kk < BK; kk += 8) {
            wmma::fragment<wmma::matrix_a, 16, 16, 8, wmma::precision::tf32, wmma::row_major> af[2];
            wmma::fragment<wmma::matrix_b, 16, 16, 8, wmma::precision::tf32, wmma::col_major> bf[2];
#pragma unroll
            for (int i = 0; i < 2; i++) {
                wmma::load_matrix_sync(af[i], Ash + (wy * 32 + i * 16) * LDA + kk, LDA);
                wmma::load_matrix_sync(bf[i], Bsh + (wx * 32 + i * 16) * LDA + kk, LDA);
            }
#pragma unroll
            for (int i = 0; i < 2; i++)
#pragma unroll
                for (int j = 0; j < 2; j++)
                    wmma::mma_sync(acc[i][j], af[i], bf[j], acc[i][j]);
        }
        __syncthreads();
    }

    if (mode == 2) {
        // Store transposed tile into Csh: Csh[d * LDC + t]
#pragma unroll
        for (int i = 0; i < 2; i++)
#pragma unroll
            for (int j = 0; j < 2; j++)
                wmma::store_matrix_sync(Csh + (wx * 32 + j * 16) * LDC + (wy * 32 + i * 16),
                                        acc[i][j], LDC, wmma::mem_col_major);
        __syncthreads();

        const int bb = m0 >> 11;        // batch (TL = 2048)
        const int t0 = m0 & (TL - 1);
        const int h = n0 >> 6;          // head (DH = 64)
        float* outbase = C + ((size_t)(bb * NH + h) * DH) * TL + t0;
#pragma unroll
        for (int i = 0; i < 8; i++) {
            int lin = tid + i * 128;
            int d = lin >> 4;
            int c4 = lin & 15;
            float4 v = *(float4*)(Csh + d * LDC + c4 * 4);
            float b = bias[n0 + d];
            v.x = tf32r(v.x + b); v.y = tf32r(v.y + b);
            v.z = tf32r(v.z + b); v.w = tf32r(v.w + b);
            *(float4*)(outbase + (size_t)d * TL + c4 * 4) = v;
        }
        return;
    }

#pragma unroll
    for (int i = 0; i < 2; i++)
#pragma unroll
        for (int j = 0; j < 2; j++)
            wmma::store_matrix_sync(Csh + (wy * 32 + i * 16) * LDC + wx * 32 + j * 16,
                                    acc[i][j], LDC, wmma::mem_row_major);
    __syncthreads();

#pragma unroll
    for (int i = 0; i < 8; i++) {
        int lin = tid + i * 128;
        int r = lin >> 4;
        int c4 = lin & 15;
        float4 v = *(float4*)(Csh + r * LDC + c4 * 4);
        int n = n0 + c4 * 4;
        float4 b4 = *(const float4*)(bias + n);
        v.x += b4.x; v.y += b4.y; v.z += b4.z; v.w += b4.w;
        if (mode == 1) {
            v.x = tf32r(v.x); v.y = tf32r(v.y);
            v.z = tf32r(v.z); v.w = tf32r(v.w);
        }
        *(float4*)(C + (size_t)(m0 + r) * Ncols + n) = v;
    }
}

// ---------------------------------------------------------------------------
// Flash attention v3: k-permuted m16n8k8 tf32.
// k-dim remap (pos q <- logical k=2q, pos q+4 <- k=2q+1) makes every B
// fragment a contiguous float2 (one LDS.64) and makes the P C-fragment
// directly reusable as the A-fragment of P·V (zero shuffles).
// V is consumed transposed ([d][t], produced by the projection GEMM).
// ALD=72 -> conflict-free LDS.64. One __syncthreads per chunk.
// ---------------------------------------------------------------------------
constexpr int ALD = 72;                 // 64 + 8 pad (floats): bank start 8r
constexpr int TSTRIDE = 64 * ALD;       // one tile (floats)
constexpr int SSTRIDE = 2 * TSTRIDE;    // one stage = K + V
constexpr int ATTN_SMEM = 2 * SSTRIDE * (int)sizeof(float);  // 73728 B

__global__ __launch_bounds__(128) void attn3_kernel(
    const float* __restrict__ Q, const float* __restrict__ K,
    const float* __restrict__ VT, float* __restrict__ Y)
{
    extern __shared__ __align__(16) float sm[];

    const int tid = threadIdx.x;
    const int lane = tid & 31;
    const int w = tid >> 5;
    const int q = lane & 3;        // thread-in-quad
    const int gr = lane >> 2;      // quad index = row-in-8
    const int s0 = blockIdx.x * 64;
    const int h = blockIdx.y;
    const int n = blockIdx.z;

    const float* Qg  = Q  + (size_t)n * SL * DM + (size_t)h * DH;
    const float* Kg  = K  + (size_t)n * TL * DM + (size_t)h * DH;
    const float* VTg = VT + ((size_t)(n * NH + h) * DH) * TL;
    float* Yg        = Y  + (size_t)n * SL * DM + (size_t)h * DH;

    // ---- Q fragments (k-permuted), scaled by 0.125*log2(e), tf32-rounded ----
    const float SCALE = 0.125f * 1.4426950408889634f;
    const int r_lo = s0 + w * 16 + gr;   // rows r_lo and r_lo+8
    unsigned qa[8][4];
#pragma unroll
    for (int kt = 0; kt < 8; kt++) {
        int d0 = kt * 8 + 2 * q;
        float2 lo = *(const float2*)(Qg + (size_t)r_lo * DM + d0);
        float2 hi = *(const float2*)(Qg + (size_t)(r_lo + 8) * DM + d0);
        qa[kt][0] = f2tf32(lo.x * SCALE);   // pos q   (k=2q),  row lo
        qa[kt][1] = f2tf32(hi.x * SCALE);   // pos q,           row hi
        qa[kt][2] = f2tf32(lo.y * SCALE);   // pos q+4 (k=2q+1),row lo
        qa[kt][3] = f2tf32(hi.y * SCALE);   // pos q+4,         row hi
    }

    float o[8][4];
#pragma unroll
    for (int j = 0; j < 8; j++)
#pragma unroll
        for (int e = 0; e < 4; e++) o[j][e] = 0.0f;

    float m_lo = -1e30f, m_hi = -1e30f, l_lo = 0.0f, l_hi = 0.0f;

    // ---- chunk loader: K rows = tokens, V rows = dims (transposed) ----
    auto load_chunk = [&](int t0, int stage) {
        float* Ksh = sm + stage * SSTRIDE;
        float* Vsh = Ksh + TSTRIDE;
#pragma unroll
        for (int i = 0; i < 8; i++) {
            int lin = tid + i * 128;        // 0..1023
            int r = lin >> 4, c4 = lin & 15;
            cp_async16(Ksh + r * ALD + c4 * 4,
                       Kg + (size_t)(t0 + r) * DM + c4 * 4);
            cp_async16(Vsh + r * ALD + c4 * 4,
                       VTg + (size_t)r * TL + t0 + c4 * 4);
        }
        cp_async_commit();
    };

    load_chunk(0, 0);

    const int NCHUNK = TL / 64;   // 32
    for (int c = 0; c < NCHUNK; c++) {
        float* Ksh = sm + (c & 1) * SSTRIDE;
        float* Vsh = Ksh + TSTRIDE;

        cp_async_wait_all();
        __syncthreads();

        if (c + 1 < NCHUNK) load_chunk((c + 1) * 64, (c + 1) & 1);

        // ---- S = Q K^T : B pair contiguous (LDS.64), log2-domain scores ----
        float s[8][4];
#pragma unroll
        for (int j = 0; j < 8; j++)
#pragma unroll
            for (int e = 0; e < 4; e++) s[j][e] = 0.0f;

        const float* Kb = Ksh + gr * ALD + 2 * q;   // + j*8*ALD + kt*8
#pragma unroll
        for (int kt = 0; kt < 8; kt++) {
#pragma unroll
            for (int j = 0; j < 8; j++) {
                float2 b = *(const float2*)(Kb + j * (8 * ALD) + kt * 8);
                mma_16n8k8(s[j][0], s[j][1], s[j][2], s[j][3],
                           qa[kt][0], qa[kt][1], qa[kt][2], qa[kt][3],
                           __float_as_uint(b.x), __float_as_uint(b.y));
            }
        }

        // ---- online softmax (registers + quad shuffles only) ----
        float mc_lo = -1e30f, mc_hi = -1e30f;
#pragma unroll
        for (int j = 0; j < 8; j++) {
            mc_lo = fmaxf(mc_lo, fmaxf(s[j][0], s[j][1]));
            mc_hi = fmaxf(mc_hi, fmaxf(s[j][2], s[j][3]));
        }
        mc_lo = fmaxf(mc_lo, __shfl_xor_sync(0xffffffffu, mc_lo, 1));
        mc_lo = fmaxf(mc_lo, __shfl_xor_sync(0xffffffffu, mc_lo, 2));
        mc_hi = fmaxf(mc_hi, __shfl_xor_sync(0xffffffffu, mc_hi, 1));
        mc_hi = fmaxf(mc_hi, __shfl_xor_sync(0xffffffffu, mc_hi, 2));

        float mn_lo = fmaxf(m_lo, mc_lo);
        float mn_hi = fmaxf(m_hi, mc_hi);
        float al = ex2f(m_lo - mn_lo);
        float ah = ex2f(m_hi - mn_hi);

        float sl = 0.0f, sh = 0.0f;
#pragma unroll
        for (int j = 0; j < 8; j++) {
            float p0 = ex2f(s[j][0] - mn_lo);
            float p1 = ex2f(s[j][1] - mn_lo);
            float p2 = ex2f(s[j][2] - mn_hi);
            float p3 = ex2f(s[j][3] - mn_hi);
            sl += p0 + p1;
            sh += p2 + p3;
            s[j][0] = __uint_as_float(f2tf32(p0));
            s[j][1] = __uint_as_float(f2tf32(p1));
            s[j][2] = __uint_as_float(f2tf32(p2));
            s[j][3] = __uint_as_float(f2tf32(p3));
        }
        sl += __shfl_xor_sync(0xffffffffu, sl, 1);
        sl += __shfl_xor_sync(0xffffffffu, sl, 2);
        sh += __shfl_xor_sync(0xffffffffu, sh, 1);
        sh += __shfl_xor_sync(0xffffffffu, sh, 2);

        l_lo = l_lo * al + sl;
        l_hi = l_hi * ah + sh;
        m_lo = mn_lo;
        m_hi = mn_hi;

#pragma unroll
        for (int j = 0; j < 8; j++) {
            o[j][0] *= al; o[j][1] *= al;
            o[j][2] *= ah; o[j][3] *= ah;
        }

        // ---- O += P V : C-fragment of P IS the A-fragment (k-permuted).
        //      a0=c0(r_lo,k=2q)  a1=c2(r_hi,k=2q)  a2=c1(r_lo,k=2q+1)  a3=c3.
        //      B from transposed V: contiguous float2 per mma. ----
        const float* Vb = Vsh + gr * ALD + 2 * q;   // + j*8*ALD + kt*8
#pragma unroll
        for (int kt = 0; kt < 8; kt++) {
            unsigned a0 = __float_as_uint(s[kt][0]);
            unsigned a1 = __float_as_uint(s[kt][2]);
            unsigned a2 = __float_as_uint(s[kt][1]);
            unsigned a3 = __float_as_uint(s[kt][3]);
#pragma unroll
            for (int j = 0; j < 8; j++) {
                float2 b = *(const float2*)(Vb + j * (8 * ALD) + kt * 8);
                mma_16n8k8(o[j][0], o[j][1], o[j][2], o[j][3],
                           a0, a1, a2, a3,
                           __float_as_uint(b.x), __float_as_uint(b.y));
            }
        }
    }

    // ---- epilogue: divide by l, write float2 pairs (cols 8j+2q, +1) ----
    float il_lo = 1.0f / l_lo;
    float il_hi = 1.0f / l_hi;
#pragma unroll
    for (int j = 0; j < 8; j++) {
        int col = 8 * j + 2 * q;
        float2 v0 = make_float2(o[j][0] * il_lo, o[j][1] * il_lo);
        *(float2*)(Yg + (size_t)r_lo * DM + col) = v0;
        float2 v1 = make_float2(o[j][2] * il_hi, o[j][3] * il_hi);
        *(float2*)(Yg + (size_t)(r_lo + 8) * DM + col) = v1;
    }
}

// ---------------------------------------------------------------------------
// Launch
// ---------------------------------------------------------------------------
extern "C" void kernel_launch(void* const* d_in, const int* in_sizes, int n_in,
                              void* d_out, int out_size)
{
    (void)in_sizes; (void)n_in; (void)out_size;
    const float* query = (const float*)d_in[0];
    const float* key   = (const float*)d_in[1];
    const float* value = (const float*)d_in[2];
    const float* Wq = (const float*)d_in[3];
    const float* bq = (const float*)d_in[4];
    const float* Wk = (const float*)d_in[5];
    const float* bk = (const float*)d_in[6];
    const float* Wv = (const float*)d_in[7];
    const float* bv = (const float*)d_in[8];
    const float* Wo = (const float*)d_in[9];
    const float* bo = (const float*)d_in[10];
    float* out = (float*)d_out;

    float *gq, *gk, *gvt, *gy;
    cudaGetSymbolAddress((void**)&gq, g_Q);
    cudaGetSymbolAddress((void**)&gk, g_K);
    cudaGetSymbolAddress((void**)&gvt, g_VT);
    cudaGetSymbolAddress((void**)&gy, g_Y);

    dim3 ggrid(DM / BN, MROWS / BM);   // (8, 128)
    gemm_xwT<<<ggrid, 128>>>(query, Wq, bq, gq,  MROWS, DM, DM, 0);
    gemm_xwT<<<ggrid, 128>>>(key,   Wk, bk, gk,  MROWS, DM, DM, 1);
    gemm_xwT<<<ggrid, 128>>>(value, Wv, bv, gvt, MROWS, DM, DM, 2);

    cudaFuncSetAttribute(attn3_kernel, cudaFuncAttributeMaxDynamicSharedMemorySize,
                         ATTN_SMEM);
    dim3 agrid(SL / 64, NH, NB);       // (32, 8, 4)
    attn3_kernel<<<agrid, 128, ATTN_SMEM>>>(gq, gk, gvt, gy);

    gemm_xwT<<<ggrid, 128>>>(gy, Wo, bo, out, MROWS, DM, DM, 0);
}

// round 5
// speedup vs baseline: 2.7413x; 1.3169x over previous
#include <cstdint>
#include <cstddef>
#include <cuda_runtime.h>
#include <cuda_bf16.h>

// Problem constants
constexpr int NB = 4;        // batch
constexpr int SL = 2048;     // query seq len
constexpr int TL = 2048;     // kv seq len
constexpr int DM = 512;      // model dim
constexpr int NH = 8;        // heads
constexpr int DH = 64;       // dim per head
constexpr int MROWS = NB * SL;  // 8192

// Scratch (allocation-free rule: __device__ globals)
__device__ float g_Q[NB * SL * DM];
__device__ float g_K[NB * TL * DM];
__device__ float g_VT[NB * NH * DH * TL];   // V transposed per head: [n][h][d][t]
__device__ float g_Y[NB * SL * DM];
// tf32-pre-rounded copies of inputs (so GEMM mainloop has zero cvt)
__device__ float g_rq[NB * SL * DM];
__device__ float g_rk[NB * TL * DM];
__device__ float g_rv[NB * TL * DM];
__device__ float g_rWq[DM * DM];
__device__ float g_rWk[DM * DM];
__device__ float g_rWv[DM * DM];
__device__ float g_rWo[DM * DM];

// ---------------------------------------------------------------------------
// Helpers
// ---------------------------------------------------------------------------
__device__ __forceinline__ unsigned f2tf32(float f) {
    unsigned u;
    asm("cvt.rna.tf32.f32 %0, %1;" : "=r"(u) : "f"(f));
    return u;
}
__device__ __forceinline__ float tf32r(float f) {
    return __uint_as_float(f2tf32(f));
}
__device__ __forceinline__ float ex2f(float x) {
    float y;
    asm("ex2.approx.f32 %0, %1;" : "=f"(y) : "f"(x));
    return y;
}
__device__ __forceinline__ void mma_16n8k8(
    float& d0, float& d1, float& d2, float& d3,
    unsigned a0, unsigned a1, unsigned a2, unsigned a3,
    unsigned b0, unsigned b1)
{
    asm volatile(
        "mma.sync.aligned.m16n8k8.row.col.f32.tf32.tf32.f32 "
        "{%0,%1,%2,%3}, {%4,%5,%6,%7}, {%8,%9}, {%0,%1,%2,%3};"
        : "+f"(d0), "+f"(d1), "+f"(d2), "+f"(d3)
        : "r"(a0), "r"(a1), "r"(a2), "r"(a3), "r"(b0), "r"(b1));
}
__device__ __forceinline__ void cp_async16(void* smem_dst, const void* gptr) {
    unsigned dst = (unsigned)__cvta_generic_to_shared(smem_dst);
    asm volatile("cp.async.cg.shared.global [%0], [%1], 16;" :: "r"(dst), "l"(gptr));
}
__device__ __forceinline__ void cp_async_commit() {
    asm volatile("cp.async.commit_group;");
}
__device__ __forceinline__ void cp_async_wait_all() {
    asm volatile("cp.async.wait_group 0;");
}

// ---------------------------------------------------------------------------
// Pre-pass: round a tensor to tf32 (rna), vectorized.
// ---------------------------------------------------------------------------
__global__ __launch_bounds__(256) void round_tf32_kernel(
    const float4* __restrict__ in, float4* __restrict__ out, int n4)
{
    int i = blockIdx.x * blockDim.x + threadIdx.x;
    if (i < n4) {
        float4 v = in[i];
        v.x = tf32r(v.x); v.y = tf32r(v.y);
        v.z = tf32r(v.z); v.w = tf32r(v.w);
        out[i] = v;
    }
}

// ---------------------------------------------------------------------------
// GEMM v2: C[M,512] = A[M,512] @ W[512,512]^T + bias.
// Tile 128x64x32, 256 threads (8 warps as 4x2), cp.async double-buffered,
// raw k-permuted m16n8k8, LDS.64 fragment loads (pad 40 -> conflict-free),
// direct float2 epilogue stores. Inputs MUST be pre-rounded to tf32.
// mode 0: fp32 out. mode 1: tf32-rounded out.
// mode 2: tf32-rounded, stored transposed per head: VT[(b*NH+h)*DH+d]*TL + t.
// ---------------------------------------------------------------------------
constexpr int GLDT = 40;                    // row pad (floats)
constexpr int G_ASZ = 128 * GLDT;           // 5120
constexpr int G_BSZ = 64 * GLDT;            // 2560
constexpr int G_STG = G_ASZ + G_BSZ;        // 7680 floats / stage
constexpr int GEMM_SMEM = 2 * G_STG * (int)sizeof(float);   // 61440 B

__global__ __launch_bounds__(256) void gemm5(
    const float* __restrict__ A, const float* __restrict__ W,
    const float* __restrict__ bias, float* __restrict__ C, int mode)
{
    extern __shared__ __align__(16) float sm[];

    const int tid = threadIdx.x;
    const int lane = tid & 31;
    const int warp = tid >> 5;
    const int q = lane & 3;
    const int gr = lane >> 2;
    const int m0 = blockIdx.y * 128;
    const int n0 = blockIdx.x * 64;
    const int mb = (warp >> 1) * 32;    // warp m offset
    const int nb = (warp & 1) * 32;     // warp n offset

    float acc[2][4][4];
#pragma unroll
    for (int i = 0; i < 2; i++)
#pragma unroll
        for (int j = 0; j < 4; j++)
#pragma unroll
            for (int e = 0; e < 4; e++) acc[i][j][e] = 0.0f;

    auto load_tiles = [&](int k0, int stage) {
        float* Ash = sm + stage * G_STG;
        float* Bsh = Ash + G_ASZ;
#pragma unroll
        for (int i = 0; i < 4; i++) {
            int lin = tid + i * 256;       // 1024 float4
            int r = lin >> 3, c4 = lin & 7;
            cp_async16(Ash + r * GLDT + c4 * 4,
                       A + (size_t)(m0 + r) * DM + k0 + c4 * 4);
        }
#pragma unroll
        for (int i = 0; i < 2; i++) {
            int lin = tid + i * 256;       // 512 float4
            int r = lin >> 3, c4 = lin & 7;
            cp_async16(Bsh + r * GLDT + c4 * 4,
                       W + (size_t)(n0 + r) * DM + k0 + c4 * 4);
        }
        cp_async_commit();
    };

    load_tiles(0, 0);

    constexpr int NKT = DM / 32;   // 16 k-tiles
    for (int t = 0; t < NKT; t++) {
        float* Ash = sm + (t & 1) * G_STG;
        float* Bsh = Ash + G_ASZ;

        cp_async_wait_all();
        __syncthreads();

        if (t + 1 < NKT) load_tiles((t + 1) * 32, (t + 1) & 1);

#pragma unroll
        for (int kt = 0; kt < 4; kt++) {
            const int ko = kt * 8 + 2 * q;
            float2 a_lo[2], a_hi[2];
#pragma unroll
            for (int i = 0; i < 2; i++) {
                const float* ap = Ash + (mb + i * 16 + gr) * GLDT + ko;
                a_lo[i] = *(const float2*)ap;
                a_hi[i] = *(const float2*)(ap + 8 * GLDT);
            }
#pragma unroll
            for (int j = 0; j < 4; j++) {
                float2 b = *(const float2*)(Bsh + (nb + j * 8 + gr) * GLDT + ko);
#pragma unroll
                for (int i = 0; i < 2; i++)
                    mma_16n8k8(acc[i][j][0], acc[i][j][1], acc[i][j][2], acc[i][j][3],
                               __float_as_uint(a_lo[i].x), __float_as_uint(a_hi[i].x),
                               __float_as_uint(a_lo[i].y), __float_as_uint(a_hi[i].y),
                               __float_as_uint(b.x), __float_as_uint(b.y));
            }
        }
        __syncthreads();
    }

    if (mode == 2) {
        // Transposed per-head store: element (t, d) -> VT[(b*NH+h)*DH + d]*TL + t
        const int bb = m0 >> 11;             // batch (TL = 2048)
        const int t0l = m0 & (TL - 1);
        const int h = n0 >> 6;               // head (DH = 64)
        float* ob = C + ((size_t)(bb * NH + h) * DH) * TL;
#pragma unroll
        for (int i = 0; i < 2; i++) {
            int t_lo = t0l + mb + i * 16 + gr;
#pragma unroll
            for (int j = 0; j < 4; j++) {
                int d = nb + j * 8 + 2 * q;
                float b0v = bias[n0 + d], b1v = bias[n0 + d + 1];
                ob[(size_t)d * TL + t_lo]           = tf32r(acc[i][j][0] + b0v);
                ob[(size_t)(d + 1) * TL + t_lo]     = tf32r(acc[i][j][1] + b1v);
                ob[(size_t)d * TL + t_lo + 8]       = tf32r(acc[i][j][2] + b0v);
                ob[(size_t)(d + 1) * TL + t_lo + 8] = tf32r(acc[i][j][3] + b1v);
            }
        }
        return;
    }

#pragma unroll
    for (int i = 0; i < 2; i++) {
        size_t row = (size_t)(m0 + mb + i * 16 + gr);
#pragma unroll
        for (int j = 0; j < 4; j++) {
            int col = n0 + nb + j * 8 + 2 * q;
            float2 bv = *(const float2*)(bias + col);
            float2 lo = make_float2(acc[i][j][0] + bv.x, acc[i][j][1] + bv.y);
            float2 hi = make_float2(acc[i][j][2] + bv.x, acc[i][j][3] + bv.y);
            if (mode == 1) {
                lo.x = tf32r(lo.x); lo.y = tf32r(lo.y);
                hi.x = tf32r(hi.x); hi.y = tf32r(hi.y);
            }
            *(float2*)(C + row * DM + col) = lo;
            *(float2*)(C + (row + 8) * DM + col) = hi;
        }
    }
}

// ---------------------------------------------------------------------------
// Flash attention v3: k-permuted m16n8k8 tf32 (unchanged from round 4 except
// the epilogue now tf32-rounds Y for the pre-rounded output GEMM).
// ---------------------------------------------------------------------------
constexpr int ALD = 72;                 // 64 + 8 pad (floats)
constexpr int TSTRIDE = 64 * ALD;
constexpr int SSTRIDE = 2 * TSTRIDE;
constexpr int ATTN_SMEM = 2 * SSTRIDE * (int)sizeof(float);  // 73728 B

__global__ __launch_bounds__(128) void attn3_kernel(
    const float* __restrict__ Q, const float* __restrict__ K,
    const float* __restrict__ VT, float* __restrict__ Y)
{
    extern __shared__ __align__(16) float sm[];

    const int tid = threadIdx.x;
    const int lane = tid & 31;
    const int w = tid >> 5;
    const int q = lane & 3;
    const int gr = lane >> 2;
    const int s0 = blockIdx.x * 64;
    const int h = blockIdx.y;
    const int n = blockIdx.z;

    const float* Qg  = Q  + (size_t)n * SL * DM + (size_t)h * DH;
    const float* Kg  = K  + (size_t)n * TL * DM + (size_t)h * DH;
    const float* VTg = VT + ((size_t)(n * NH + h) * DH) * TL;
    float* Yg        = Y  + (size_t)n * SL * DM + (size_t)h * DH;

    const float SCALE = 0.125f * 1.4426950408889634f;
    const int r_lo = s0 + w * 16 + gr;
    unsigned qa[8][4];
#pragma unroll
    for (int kt = 0; kt < 8; kt++) {
        int d0 = kt * 8 + 2 * q;
        float2 lo = *(const float2*)(Qg + (size_t)r_lo * DM + d0);
        float2 hi = *(const float2*)(Qg + (size_t)(r_lo + 8) * DM + d0);
        qa[kt][0] = f2tf32(lo.x * SCALE);
        qa[kt][1] = f2tf32(hi.x * SCALE);
        qa[kt][2] = f2tf32(lo.y * SCALE);
        qa[kt][3] = f2tf32(hi.y * SCALE);
    }

    float o[8][4];
#pragma unroll
    for (int j = 0; j < 8; j++)
#pragma unroll
        for (int e = 0; e < 4; e++) o[j][e] = 0.0f;

    float m_lo = -1e30f, m_hi = -1e30f, l_lo = 0.0f, l_hi = 0.0f;

    auto load_chunk = [&](int t0, int stage) {
        float* Ksh = sm + stage * SSTRIDE;
        float* Vsh = Ksh + TSTRIDE;
#pragma unroll
        for (int i = 0; i < 8; i++) {
            int lin = tid + i * 128;
            int r = lin >> 4, c4 = lin & 15;
            cp_async16(Ksh + r * ALD + c4 * 4,
                       Kg + (size_t)(t0 + r) * DM + c4 * 4);
            cp_async16(Vsh + r * ALD + c4 * 4,
                       VTg + (size_t)r * TL + t0 + c4 * 4);
        }
        cp_async_commit();
    };

    load_chunk(0, 0);

    const int NCHUNK = TL / 64;
    for (int c = 0; c < NCHUNK; c++) {
        float* Ksh = sm + (c & 1) * SSTRIDE;
        float* Vsh = Ksh + TSTRIDE;

        cp_async_wait_all();
        __syncthreads();

        if (c + 1 < NCHUNK) load_chunk((c + 1) * 64, (c + 1) & 1);

        float s[8][4];
#pragma unroll
        for (int j = 0; j < 8; j++)
#pragma unroll
            for (int e = 0; e < 4; e++) s[j][e] = 0.0f;

        const float* Kb = Ksh + gr * ALD + 2 * q;
#pragma unroll
        for (int kt = 0; kt < 8; kt++) {
#pragma unroll
            for (int j = 0; j < 8; j++) {
                float2 b = *(const float2*)(Kb + j * (8 * ALD) + kt * 8);
                mma_16n8k8(s[j][0], s[j][1], s[j][2], s[j][3],
                           qa[kt][0], qa[kt][1], qa[kt][2], qa[kt][3],
                           __float_as_uint(b.x), __float_as_uint(b.y));
            }
        }

        float mc_lo = -1e30f, mc_hi = -1e30f;
#pragma unroll
        for (int j = 0; j < 8; j++) {
            mc_lo = fmaxf(mc_lo, fmaxf(s[j][0], s[j][1]));
            mc_hi = fmaxf(mc_hi, fmaxf(s[j][2], s[j][3]));
        }
        mc_lo = fmaxf(mc_lo, __shfl_xor_sync(0xffffffffu, mc_lo, 1));
        mc_lo = fmaxf(mc_lo, __shfl_xor_sync(0xffffffffu, mc_lo, 2));
        mc_hi = fmaxf(mc_hi, __shfl_xor_sync(0xffffffffu, mc_hi, 1));
        mc_hi = fmaxf(mc_hi, __shfl_xor_sync(0xffffffffu, mc_hi, 2));

        float mn_lo = fmaxf(m_lo, mc_lo);
        float mn_hi = fmaxf(m_hi, mc_hi);
        float al = ex2f(m_lo - mn_lo);
        float ah = ex2f(m_hi - mn_hi);

        float sl = 0.0f, sh = 0.0f;
#pragma unroll
        for (int j = 0; j < 8; j++) {
            float p0 = ex2f(s[j][0] - mn_lo);
            float p1 = ex2f(s[j][1] - mn_lo);
            float p2 = ex2f(s[j][2] - mn_hi);
            float p3 = ex2f(s[j][3] - mn_hi);
            sl += p0 + p1;
            sh += p2 + p3;
            s[j][0] = __uint_as_float(f2tf32(p0));
            s[j][1] = __uint_as_float(f2tf32(p1));
            s[j][2] = __uint_as_float(f2tf32(p2));
            s[j][3] = __uint_as_float(f2tf32(p3));
        }
        sl += __shfl_xor_sync(0xffffffffu, sl, 1);
        sl += __shfl_xor_sync(0xffffffffu, sl, 2);
        sh += __shfl_xor_sync(0xffffffffu, sh, 1);
        sh += __shfl_xor_sync(0xffffffffu, sh, 2);

        l_lo = l_lo * al + sl;
        l_hi = l_hi * ah + sh;
        m_lo = mn_lo;
        m_hi = mn_hi;

#pragma unroll
        for (int j = 0; j < 8; j++) {
            o[j][0] *= al; o[j][1] *= al;
            o[j][2] *= ah; o[j][3] *= ah;
        }

        const float* Vb = Vsh + gr * ALD + 2 * q;
#pragma unroll
        for (int kt = 0; kt < 8; kt++) {
            unsigned a0 = __float_as_uint(s[kt][0]);
            unsigned a1 = __float_as_uint(s[kt][2]);
            unsigned a2 = __float_as_uint(s[kt][1]);
            unsigned a3 = __float_as_uint(s[kt][3]);
#pragma unroll
            for (int j = 0; j < 8; j++) {
                float2 b = *(const float2*)(Vb + j * (8 * ALD) + kt * 8);
                mma_16n8k8(o[j][0], o[j][1], o[j][2], o[j][3],
                           a0, a1, a2, a3,
                           __float_as_uint(b.x), __float_as_uint(b.y));
            }
        }
    }

    // ---- epilogue: divide by l, tf32-round (feeds pre-rounded out GEMM) ----
    float il_lo = 1.0f / l_lo;
    float il_hi = 1.0f / l_hi;
#pragma unroll
    for (int j = 0; j < 8; j++) {
        int col = 8 * j + 2 * q;
        float2 v0 = make_float2(tf32r(o[j][0] * il_lo), tf32r(o[j][1] * il_lo));
        *(float2*)(Yg + (size_t)r_lo * DM + col) = v0;
        float2 v1 = make_float2(tf32r(o[j][2] * il_hi), tf32r(o[j][3] * il_hi));
        *(float2*)(Yg + (size_t)(r_lo + 8) * DM + col) = v1;
    }
}

// ---------------------------------------------------------------------------
// Launch
// ---------------------------------------------------------------------------
extern "C" void kernel_launch(void* const* d_in, const int* in_sizes, int n_in,
                              void* d_out, int out_size)
{
    (void)in_sizes; (void)n_in; (void)out_size;
    const float* query = (const float*)d_in[0];
    const float* key   = (const float*)d_in[1];
    const float* value = (const float*)d_in[2];
    const float* Wq = (const float*)d_in[3];
    const float* bq = (const float*)d_in[4];
    const float* Wk = (const float*)d_in[5];
    const float* bk = (const float*)d_in[6];
    const float* Wv = (const float*)d_in[7];
    const float* bv = (const float*)d_in[8];
    const float* Wo = (const float*)d_in[9];
    const float* bo = (const float*)d_in[10];
    float* out = (float*)d_out;

    float *gq, *gk, *gvt, *gy;
    float *rq, *rk, *rv, *rWq, *rWk, *rWv, *rWo;
    cudaGetSymbolAddress((void**)&gq,  g_Q);
    cudaGetSymbolAddress((void**)&gk,  g_K);
    cudaGetSymbolAddress((void**)&gvt, g_VT);
    cudaGetSymbolAddress((void**)&gy,  g_Y);
    cudaGetSymbolAddress((void**)&rq,  g_rq);
    cudaGetSymbolAddress((void**)&rk,  g_rk);
    cudaGetSymbolAddress((void**)&rv,  g_rv);
    cudaGetSymbolAddress((void**)&rWq, g_rWq);
    cudaGetSymbolAddress((void**)&rWk, g_rWk);
    cudaGetSymbolAddress((void**)&rWv, g_rWv);
    cudaGetSymbolAddress((void**)&rWo, g_rWo);

    // ---- pre-pass: tf32-round all GEMM inputs ----
    const int big4 = NB * SL * DM / 4;     // 1048576 float4
    const int w4   = DM * DM / 4;          // 65536 float4
    round_tf32_kernel<<<(big4 + 255) / 256, 256>>>((const float4*)query, (float4*)rq, big4);
    round_tf32_kernel<<<(big4 + 255) / 256, 256>>>((const float4*)key,   (float4*)rk, big4);
    round_tf32_kernel<<<(big4 + 255) / 256, 256>>>((const float4*)value, (float4*)rv, big4);
    round_tf32_kernel<<<(w4 + 255) / 256, 256>>>((const float4*)Wq, (float4*)rWq, w4);
    round_tf32_kernel<<<(w4 + 255) / 256, 256>>>((const float4*)Wk, (float4*)rWk, w4);
    round_tf32_kernel<<<(w4 + 255) / 256, 256>>>((const float4*)Wv, (float4*)rWv, w4);
    round_tf32_kernel<<<(w4 + 255) / 256, 256>>>((const float4*)Wo, (float4*)rWo, w4);

    cudaFuncSetAttribute(gemm5, cudaFuncAttributeMaxDynamicSharedMemorySize, GEMM_SMEM);
    cudaFuncSetAttribute(attn3_kernel, cudaFuncAttributeMaxDynamicSharedMemorySize,
                         ATTN_SMEM);

    dim3 ggrid(DM / 64, MROWS / 128);   // (8, 64)
    gemm5<<<ggrid, 256, GEMM_SMEM>>>(rq, rWq, bq, gq,  0);
    gemm5<<<ggrid, 256, GEMM_SMEM>>>(rk, rWk, bk, gk,  1);
    gemm5<<<ggrid, 256, GEMM_SMEM>>>(rv, rWv, bv, gvt, 2);

    dim3 agrid(SL / 64, NH, NB);        // (32, 8, 4)
    attn3_kernel<<<agrid, 128, ATTN_SMEM>>>(gq, gk, gvt, gy);

    gemm5<<<ggrid, 256, GEMM_SMEM>>>(gy, rWo, bo, out, 0);
}

// round 6
// speedup vs baseline: 2.8929x; 1.0553x over previous
#include <cstdint>
#include <cstddef>
#include <cuda_runtime.h>
#include <cuda_bf16.h>

// Problem constants
constexpr int NB = 4;
constexpr int SL = 2048;
constexpr int TL = 2048;
constexpr int DM = 512;
constexpr int NH = 8;
constexpr int DH = 64;
constexpr int MROWS = NB * SL;  // 8192

// Scratch (allocation-free rule: __device__ globals)
__device__ float g_Q[NB * SL * DM];
__device__ float g_K[NB * TL * DM];
__device__ float g_VT[NB * NH * DH * TL];
__device__ float g_Y[NB * SL * DM];
__device__ float g_rq[NB * SL * DM];
__device__ float g_rk[NB * TL * DM];
__device__ float g_rv[NB * TL * DM];
__device__ float g_rWq[DM * DM];
__device__ float g_rWk[DM * DM];
__device__ float g_rWv[DM * DM];
__device__ float g_rWo[DM * DM];

// ---------------------------------------------------------------------------
// Helpers
// ---------------------------------------------------------------------------
__device__ __forceinline__ unsigned f2tf32(float f) {
    unsigned u;
    asm("cvt.rna.tf32.f32 %0, %1;" : "=r"(u) : "f"(f));
    return u;
}
__device__ __forceinline__ float tf32r(float f) {
    return __uint_as_float(f2tf32(f));
}
__device__ __forceinline__ float ex2f(float x) {
    float y;
    asm("ex2.approx.f32 %0, %1;" : "=f"(y) : "f"(x));
    return y;
}
__device__ __forceinline__ void mma_16n8k8(
    float& d0, float& d1, float& d2, float& d3,
    unsigned a0, unsigned a1, unsigned a2, unsigned a3,
    unsigned b0, unsigned b1)
{
    asm volatile(
        "mma.sync.aligned.m16n8k8.row.col.f32.tf32.tf32.f32 "
        "{%0,%1,%2,%3}, {%4,%5,%6,%7}, {%8,%9}, {%0,%1,%2,%3};"
        : "+f"(d0), "+f"(d1), "+f"(d2), "+f"(d3)
        : "r"(a0), "r"(a1), "r"(a2), "r"(a3), "r"(b0), "r"(b1));
}
__device__ __forceinline__ void cp_async16(void* smem_dst, const void* gptr) {
    unsigned dst = (unsigned)__cvta_generic_to_shared(smem_dst);
    asm volatile("cp.async.cg.shared.global [%0], [%1], 16;" :: "r"(dst), "l"(gptr));
}
__device__ __forceinline__ void cp_async_commit() {
    asm volatile("cp.async.commit_group;");
}
__device__ __forceinline__ void cp_async_wait_all() {
    asm volatile("cp.async.wait_group 0;");
}

// ---------------------------------------------------------------------------
// Fused pre-pass: tf32-round all 7 GEMM inputs in ONE launch.
// Segments: 3 big tensors (1048576 float4 each) + 4 weights (65536 each).
// ---------------------------------------------------------------------------
constexpr int BIG4 = NB * SL * DM / 4;   // 1048576
constexpr int W4   = DM * DM / 4;        // 65536
constexpr int TOTAL4 = 3 * BIG4 + 4 * W4;

__global__ __launch_bounds__(256) void round_all_kernel(
    const float4* __restrict__ q,  float4* __restrict__ rq,
    const float4* __restrict__ k,  float4* __restrict__ rk,
    const float4* __restrict__ v,  float4* __restrict__ rv,
    const float4* __restrict__ wq, float4* __restrict__ rwq,
    const float4* __restrict__ wk, float4* __restrict__ rwk,
    const float4* __restrict__ wv, float4* __restrict__ rwv,
    const float4* __restrict__ wo, float4* __restrict__ rwo)
{
    int idx = blockIdx.x * 256 + threadIdx.x;
    if (idx >= TOTAL4) return;
    const float4* src;
    float4* dst;
    int off;
    if (idx < BIG4)            { src = q;  dst = rq;  off = idx; }
    else if (idx < 2 * BIG4)   { src = k;  dst = rk;  off = idx - BIG4; }
    else if (idx < 3 * BIG4)   { src = v;  dst = rv;  off = idx - 2 * BIG4; }
    else {
        int w = idx - 3 * BIG4;
        int seg = w >> 16;             // 65536 per weight
        off = w & 65535;
        switch (seg) {
            case 0: src = wq; dst = rwq; break;
            case 1: src = wk; dst = rwk; break;
            case 2: src = wv; dst = rwv; break;
            default: src = wo; dst = rwo; break;
        }
    }
    float4 x = src[off];
    x.x = tf32r(x.x); x.y = tf32r(x.y);
    x.z = tf32r(x.z); x.w = tf32r(x.w);
    dst[off] = x;
}

// ---------------------------------------------------------------------------
// GEMM v3: C[M,512] = A[M,512] @ W[512,512]^T + bias.
// Tile 128x64x32, 256 threads, cp.async double-buffered, 4-wide k-permuted
// m16n8k8 with LDS.128 fragment loads (GLDT=48: rowstride 192B == 64 mod 128
// -> conflict-free phases). QKV fused via blockIdx.z (GemmArgs structs).
// mode 0: fp32 out. mode 1: tf32 out. mode 2: tf32 out transposed per head.
// ---------------------------------------------------------------------------
struct GemmArgs {
    const float* A;
    const float* W;
    const float* bias;
    float* C;
    int mode;
};

constexpr int GLDT = 48;
constexpr int G_ASZ = 128 * GLDT;           // 6144 floats
constexpr int G_BSZ = 64 * GLDT;            // 3072 floats
constexpr int G_STG = G_ASZ + G_BSZ;        // 9216 floats
constexpr int GEMM_SMEM = 2 * G_STG * (int)sizeof(float);   // 73728 B

__global__ __launch_bounds__(256) void gemm6(
    GemmArgs ga0, GemmArgs ga1, GemmArgs ga2)
{
    extern __shared__ __align__(16) float sm[];

    const GemmArgs& ga = (blockIdx.z == 0) ? ga0 : (blockIdx.z == 1) ? ga1 : ga2;
    const float* __restrict__ A = ga.A;
    const float* __restrict__ W = ga.W;
    const float* __restrict__ bias = ga.bias;
    float* __restrict__ C = ga.C;
    const int mode = ga.mode;

    const int tid = threadIdx.x;
    const int lane = tid & 31;
    const int warp = tid >> 5;
    const int q = lane & 3;
    const int gr = lane >> 2;
    const int m0 = blockIdx.y * 128;
    const int n0 = blockIdx.x * 64;
    const int mb = (warp >> 1) * 32;
    const int nb = (warp & 1) * 32;

    float acc[2][4][4];
#pragma unroll
    for (int i = 0; i < 2; i++)
#pragma unroll
        for (int j = 0; j < 4; j++)
#pragma unroll
            for (int e = 0; e < 4; e++) acc[i][j][e] = 0.0f;

    auto load_tiles = [&](int k0, int stage) {
        float* Ash = sm + stage * G_STG;
        float* Bsh = Ash + G_ASZ;
#pragma unroll
        for (int i = 0; i < 4; i++) {
            int lin = tid + i * 256;       // 1024 float4
            int r = lin >> 3, c4 = lin & 7;
            cp_async16(Ash + r * GLDT + c4 * 4,
                       A + (size_t)(m0 + r) * DM + k0 + c4 * 4);
        }
#pragma unroll
        for (int i = 0; i < 2; i++) {
            int lin = tid + i * 256;       // 512 float4
            int r = lin >> 3, c4 = lin & 7;
            cp_async16(Bsh + r * GLDT + c4 * 4,
                       W + (size_t)(n0 + r) * DM + k0 + c4 * 4);
        }
        cp_async_commit();
    };

    load_tiles(0, 0);

    constexpr int NKT = DM / 32;   // 16
    for (int t = 0; t < NKT; t++) {
        float* Ash = sm + (t & 1) * G_STG;
        float* Bsh = Ash + G_ASZ;

        cp_async_wait_all();
        __syncthreads();

        if (t + 1 < NKT) load_tiles((t + 1) * 32, (t + 1) & 1);

#pragma unroll
        for (int kk = 0; kk < 2; kk++) {
            const int ko = kk * 16 + 4 * q;
            float4 alo[2], ahi[2], bb[4];
#pragma unroll
            for (int i = 0; i < 2; i++) {
                const float* ap = Ash + (mb + i * 16 + gr) * GLDT + ko;
                alo[i] = *(const float4*)ap;
                ahi[i] = *(const float4*)(ap + 8 * GLDT);
            }
#pragma unroll
            for (int j = 0; j < 4; j++)
                bb[j] = *(const float4*)(Bsh + (nb + j * 8 + gr) * GLDT + ko);
#pragma unroll
            for (int j = 0; j < 4; j++)
#pragma unroll
                for (int i = 0; i < 2; i++) {
                    mma_16n8k8(acc[i][j][0], acc[i][j][1], acc[i][j][2], acc[i][j][3],
                               __float_as_uint(alo[i].x), __float_as_uint(ahi[i].x),
                               __float_as_uint(alo[i].y), __float_as_uint(ahi[i].y),
                               __float_as_uint(bb[j].x),  __float_as_uint(bb[j].y));
                    mma_16n8k8(acc[i][j][0], acc[i][j][1], acc[i][j][2], acc[i][j][3],
                               __float_as_uint(alo[i].z), __float_as_uint(ahi[i].z),
                               __float_as_uint(alo[i].w), __float_as_uint(ahi[i].w),
                               __float_as_uint(bb[j].z),  __float_as_uint(bb[j].w));
                }
        }
        __syncthreads();
    }

    if (mode == 2) {
        const int bb2 = m0 >> 11;            // batch (TL = 2048)
        const int t0l = m0 & (TL - 1);
        const int h = n0 >> 6;               // head
        float* ob = C + ((size_t)(bb2 * NH + h) * DH) * TL;
#pragma unroll
        for (int i = 0; i < 2; i++) {
            int t_lo = t0l + mb + i * 16 + gr;
#pragma unroll
            for (int j = 0; j < 4; j++) {
                int d = nb + j * 8 + 2 * q;
                float b0v = bias[n0 + d], b1v = bias[n0 + d + 1];
                ob[(size_t)d * TL + t_lo]           = tf32r(acc[i][j][0] + b0v);
                ob[(size_t)(d + 1) * TL + t_lo]     = tf32r(acc[i][j][1] + b1v);
                ob[(size_t)d * TL + t_lo + 8]       = tf32r(acc[i][j][2] + b0v);
                ob[(size_t)(d + 1) * TL + t_lo + 8] = tf32r(acc[i][j][3] + b1v);
            }
        }
        return;
    }

#pragma unroll
    for (int i = 0; i < 2; i++) {
        size_t row = (size_t)(m0 + mb + i * 16 + gr);
#pragma unroll
        for (int j = 0; j < 4; j++) {
            int col = n0 + nb + j * 8 + 2 * q;
            float2 bv = *(const float2*)(bias + col);
            float2 lo = make_float2(acc[i][j][0] + bv.x, acc[i][j][1] + bv.y);
            float2 hi = make_float2(acc[i][j][2] + bv.x, acc[i][j][3] + bv.y);
            if (mode == 1) {
                lo.x = tf32r(lo.x); lo.y = tf32r(lo.y);
                hi.x = tf32r(hi.x); hi.y = tf32r(hi.y);
            }
            *(float2*)(C + row * DM + col) = lo;
            *(float2*)(C + (row + 8) * DM + col) = hi;
        }
    }
}

// ---------------------------------------------------------------------------
// Flash attention v3 (unchanged from round 5 — the proven 249us kernel).
// ---------------------------------------------------------------------------
constexpr int ALD = 72;
constexpr int TSTRIDE = 64 * ALD;
constexpr int SSTRIDE = 2 * TSTRIDE;
constexpr int ATTN_SMEM = 2 * SSTRIDE * (int)sizeof(float);  // 73728 B

__global__ __launch_bounds__(128) void attn3_kernel(
    const float* __restrict__ Q, const float* __restrict__ K,
    const float* __restrict__ VT, float* __restrict__ Y)
{
    extern __shared__ __align__(16) float sm[];

    const int tid = threadIdx.x;
    const int lane = tid & 31;
    const int w = tid >> 5;
    const int q = lane & 3;
    const int gr = lane >> 2;
    const int s0 = blockIdx.x * 64;
    const int h = blockIdx.y;
    const int n = blockIdx.z;

    const float* Qg  = Q  + (size_t)n * SL * DM + (size_t)h * DH;
    const float* Kg  = K  + (size_t)n * TL * DM + (size_t)h * DH;
    const float* VTg = VT + ((size_t)(n * NH + h) * DH) * TL;
    float* Yg        = Y  + (size_t)n * SL * DM + (size_t)h * DH;

    const float SCALE = 0.125f * 1.4426950408889634f;
    const int r_lo = s0 + w * 16 + gr;
    unsigned qa[8][4];
#pragma unroll
    for (int kt = 0; kt < 8; kt++) {
        int d0 = kt * 8 + 2 * q;
        float2 lo = *(const float2*)(Qg + (size_t)r_lo * DM + d0);
        float2 hi = *(const float2*)(Qg + (size_t)(r_lo + 8) * DM + d0);
        qa[kt][0] = f2tf32(lo.x * SCALE);
        qa[kt][1] = f2tf32(hi.x * SCALE);
        qa[kt][2] = f2tf32(lo.y * SCALE);
        qa[kt][3] = f2tf32(hi.y * SCALE);
    }

    float o[8][4];
#pragma unroll
    for (int j = 0; j < 8; j++)
#pragma unroll
        for (int e = 0; e < 4; e++) o[j][e] = 0.0f;

    float m_lo = -1e30f, m_hi = -1e30f, l_lo = 0.0f, l_hi = 0.0f;

    auto load_chunk = [&](int t0, int stage) {
        float* Ksh = sm + stage * SSTRIDE;
        float* Vsh = Ksh + TSTRIDE;
#pragma unroll
        for (int i = 0; i < 8; i++) {
            int lin = tid + i * 128;
            int r = lin >> 4, c4 = lin & 15;
            cp_async16(Ksh + r * ALD + c4 * 4,
                       Kg + (size_t)(t0 + r) * DM + c4 * 4);
            cp_async16(Vsh + r * ALD + c4 * 4,
                       VTg + (size_t)r * TL + t0 + c4 * 4);
        }
        cp_async_commit();
    };

    load_chunk(0, 0);

    const int NCHUNK = TL / 64;
    for (int c = 0; c < NCHUNK; c++) {
        float* Ksh = sm + (c & 1) * SSTRIDE;
        float* Vsh = Ksh + TSTRIDE;

        cp_async_wait_all();
        __syncthreads();

        if (c + 1 < NCHUNK) load_chunk((c + 1) * 64, (c + 1) & 1);

        float s[8][4];
#pragma unroll
        for (int j = 0; j < 8; j++)
#pragma unroll
            for (int e = 0; e < 4; e++) s[j][e] = 0.0f;

        const float* Kb = Ksh + gr * ALD + 2 * q;
#pragma unroll
        for (int kt = 0; kt < 8; kt++) {
#pragma unroll
            for (int j = 0; j < 8; j++) {
                float2 b = *(const float2*)(Kb + j * (8 * ALD) + kt * 8);
                mma_16n8k8(s[j][0], s[j][1], s[j][2], s[j][3],
                           qa[kt][0], qa[kt][1], qa[kt][2], qa[kt][3],
                           __float_as_uint(b.x), __float_as_uint(b.y));
            }
        }

        float mc_lo = -1e30f, mc_hi = -1e30f;
#pragma unroll
        for (int j = 0; j < 8; j++) {
            mc_lo = fmaxf(mc_lo, fmaxf(s[j][0], s[j][1]));
            mc_hi = fmaxf(mc_hi, fmaxf(s[j][2], s[j][3]));
        }
        mc_lo = fmaxf(mc_lo, __shfl_xor_sync(0xffffffffu, mc_lo, 1));
        mc_lo = fmaxf(mc_lo, __shfl_xor_sync(0xffffffffu, mc_lo, 2));
        mc_hi = fmaxf(mc_hi, __shfl_xor_sync(0xffffffffu, mc_hi, 1));
        mc_hi = fmaxf(mc_hi, __shfl_xor_sync(0xffffffffu, mc_hi, 2));

        float mn_lo = fmaxf(m_lo, mc_lo);
        float mn_hi = fmaxf(m_hi, mc_hi);
        float al = ex2f(m_lo - mn_lo);
        float ah = ex2f(m_hi - mn_hi);

        float sl = 0.0f, sh = 0.0f;
#pragma unroll
        for (int j = 0; j < 8; j++) {
            float p0 = ex2f(s[j][0] - mn_lo);
            float p1 = ex2f(s[j][1] - mn_lo);
            float p2 = ex2f(s[j][2] - mn_hi);
            float p3 = ex2f(s[j][3] - mn_hi);
            sl += p0 + p1;
            sh += p2 + p3;
            s[j][0] = __uint_as_float(f2tf32(p0));
            s[j][1] = __uint_as_float(f2tf32(p1));
            s[j][2] = __uint_as_float(f2tf32(p2));
            s[j][3] = __uint_as_float(f2tf32(p3));
        }
        sl += __shfl_xor_sync(0xffffffffu, sl, 1);
        sl += __shfl_xor_sync(0xffffffffu, sl, 2);
        sh += __shfl_xor_sync(0xffffffffu, sh, 1);
        sh += __shfl_xor_sync(0xffffffffu, sh, 2);

        l_lo = l_lo * al + sl;
        l_hi = l_hi * ah + sh;
        m_lo = mn_lo;
        m_hi = mn_hi;

#pragma unroll
        for (int j = 0; j < 8; j++) {
            o[j][0] *= al; o[j][1] *= al;
            o[j][2] *= ah; o[j][3] *= ah;
        }

        const float* Vb = Vsh + gr * ALD + 2 * q;
#pragma unroll
        for (int kt = 0; kt < 8; kt++) {
            unsigned a0 = __float_as_uint(s[kt][0]);
            unsigned a1 = __float_as_uint(s[kt][2]);
            unsigned a2 = __float_as_uint(s[kt][1]);
            unsigned a3 = __float_as_uint(s[kt][3]);
#pragma unroll
            for (int j = 0; j < 8; j++) {
                float2 b = *(const float2*)(Vb + j * (8 * ALD) + kt * 8);
                mma_16n8k8(o[j][0], o[j][1], o[j][2], o[j][3],
                           a0, a1, a2, a3,
                           __float_as_uint(b.x), __float_as_uint(b.y));
            }
        }
    }

    float il_lo = 1.0f / l_lo;
    float il_hi = 1.0f / l_hi;
#pragma unroll
    for (int j = 0; j < 8; j++) {
        int col = 8 * j + 2 * q;
        float2 v0 = make_float2(tf32r(o[j][0] * il_lo), tf32r(o[j][1] * il_lo));
        *(float2*)(Yg + (size_t)r_lo * DM + col) = v0;
        float2 v1 = make_float2(tf32r(o[j][2] * il_hi), tf32r(o[j][3] * il_hi));
        *(float2*)(Yg + (size_t)(r_lo + 8) * DM + col) = v1;
    }
}

// ---------------------------------------------------------------------------
// Launch
// ---------------------------------------------------------------------------
extern "C" void kernel_launch(void* const* d_in, const int* in_sizes, int n_in,
                              void* d_out, int out_size)
{
    (void)in_sizes; (void)n_in; (void)out_size;
    const float* query = (const float*)d_in[0];
    const float* key   = (const float*)d_in[1];
    const float* value = (const float*)d_in[2];
    const float* Wq = (const float*)d_in[3];
    const float* bq = (const float*)d_in[4];
    const float* Wk = (const float*)d_in[5];
    const float* bk = (const float*)d_in[6];
    const float* Wv = (const float*)d_in[7];
    const float* bv = (const float*)d_in[8];
    const float* Wo = (const float*)d_in[9];
    const float* bo = (const float*)d_in[10];
    float* out = (float*)d_out;

    float *gq, *gk, *gvt, *gy;
    float *rq, *rk, *rv, *rWq, *rWk, *rWv, *rWo;
    cudaGetSymbolAddress((void**)&gq,  g_Q);
    cudaGetSymbolAddress((void**)&gk,  g_K);
    cudaGetSymbolAddress((void**)&gvt, g_VT);
    cudaGetSymbolAddress((void**)&gy,  g_Y);
    cudaGetSymbolAddress((void**)&rq,  g_rq);
    cudaGetSymbolAddress((void**)&rk,  g_rk);
    cudaGetSymbolAddress((void**)&rv,  g_rv);
    cudaGetSymbolAddress((void**)&rWq, g_rWq);
    cudaGetSymbolAddress((void**)&rWk, g_rWk);
    cudaGetSymbolAddress((void**)&rWv, g_rWv);
    cudaGetSymbolAddress((void**)&rWo, g_rWo);

    // ---- fused pre-pass (one launch) ----
    round_all_kernel<<<(TOTAL4 + 255) / 256, 256>>>(
        (const float4*)query, (float4*)rq,
        (const float4*)key,   (float4*)rk,
        (const float4*)value, (float4*)rv,
        (const float4*)Wq, (float4*)rWq,
        (const float4*)Wk, (float4*)rWk,
        (const float4*)Wv, (float4*)rWv,
        (const float4*)Wo, (float4*)rWo);

    cudaFuncSetAttribute(gemm6, cudaFuncAttributeMaxDynamicSharedMemorySize, GEMM_SMEM);
    cudaFuncSetAttribute(attn3_kernel, cudaFuncAttributeMaxDynamicSharedMemorySize,
                         ATTN_SMEM);

    // ---- fused QKV projection (one launch, z selects operand set) ----
    GemmArgs aq{rq, rWq, bq, gq,  0};
    GemmArgs ak{rk, rWk, bk, gk,  1};
    GemmArgs av{rv, rWv, bv, gvt, 2};
    dim3 qkvgrid(DM / 64, MROWS / 128, 3);   // (8, 64, 3)
    gemm6<<<qkvgrid, 256, GEMM_SMEM>>>(aq, ak, av);

    dim3 agrid(SL / 64, NH, NB);             // (32, 8, 4)
    attn3_kernel<<<agrid, 128, ATTN_SMEM>>>(gq, gk, gvt, gy);

    // ---- output projection ----
    GemmArgs ao{gy, rWo, bo, out, 0};
    dim3 ogrid(DM / 64, MROWS / 128, 1);
    gemm6<<<ogrid, 256, GEMM_SMEM>>>(ao, ao, ao);
}

// round 7
// speedup vs baseline: 3.0980x; 1.0709x over previous
#include <cstdint>
#include <cstddef>
#include <cuda_runtime.h>
#include <cuda_bf16.h>

// Problem constants
constexpr int NB = 4;
constexpr int SL = 2048;
constexpr int TL = 2048;
constexpr int DM = 512;
constexpr int NH = 8;
constexpr int DH = 64;
constexpr int MROWS = NB * SL;  // 8192

// Scratch (allocation-free rule: __device__ globals)
__device__ float g_Q[NB * SL * DM];
__device__ float g_K[NB * TL * DM];
__device__ float g_VT[NB * NH * DH * TL];
__device__ float g_Y[NB * SL * DM];
__device__ float g_rq[NB * SL * DM];
__device__ float g_rk[NB * TL * DM];
__device__ float g_rv[NB * TL * DM];
__device__ float g_rWq[DM * DM];
__device__ float g_rWk[DM * DM];
__device__ float g_rWv[DM * DM];
__device__ float g_rWo[DM * DM];

// ---------------------------------------------------------------------------
// Helpers
// ---------------------------------------------------------------------------
__device__ __forceinline__ unsigned f2tf32(float f) {
    unsigned u;
    asm("cvt.rna.tf32.f32 %0, %1;" : "=r"(u) : "f"(f));
    return u;
}
__device__ __forceinline__ float tf32r(float f) {
    return __uint_as_float(f2tf32(f));
}
__device__ __forceinline__ float ex2f(float x) {
    float y;
    asm("ex2.approx.f32 %0, %1;" : "=f"(y) : "f"(x));
    return y;
}
__device__ __forceinline__ void mma_16n8k8(
    float& d0, float& d1, float& d2, float& d3,
    unsigned a0, unsigned a1, unsigned a2, unsigned a3,
    unsigned b0, unsigned b1)
{
    asm volatile(
        "mma.sync.aligned.m16n8k8.row.col.f32.tf32.tf32.f32 "
        "{%0,%1,%2,%3}, {%4,%5,%6,%7}, {%8,%9}, {%0,%1,%2,%3};"
        : "+f"(d0), "+f"(d1), "+f"(d2), "+f"(d3)
        : "r"(a0), "r"(a1), "r"(a2), "r"(a3), "r"(b0), "r"(b1));
}
__device__ __forceinline__ void cp_async16(void* smem_dst, const void* gptr) {
    unsigned dst = (unsigned)__cvta_generic_to_shared(smem_dst);
    asm volatile("cp.async.cg.shared.global [%0], [%1], 16;" :: "r"(dst), "l"(gptr));
}
__device__ __forceinline__ void cp_async_commit() {
    asm volatile("cp.async.commit_group;");
}
__device__ __forceinline__ void cp_async_wait_all() {
    asm volatile("cp.async.wait_group 0;");
}

// ---------------------------------------------------------------------------
// Fused pre-pass: tf32-round all 7 GEMM inputs in ONE launch.
// ---------------------------------------------------------------------------
constexpr int BIG4 = NB * SL * DM / 4;   // 1048576
constexpr int W4   = DM * DM / 4;        // 65536
constexpr int TOTAL4 = 3 * BIG4 + 4 * W4;

__global__ __launch_bounds__(256) void round_all_kernel(
    const float4* __restrict__ q,  float4* __restrict__ rq,
    const float4* __restrict__ k,  float4* __restrict__ rk,
    const float4* __restrict__ v,  float4* __restrict__ rv,
    const float4* __restrict__ wq, float4* __restrict__ rwq,
    const float4* __restrict__ wk, float4* __restrict__ rwk,
    const float4* __restrict__ wv, float4* __restrict__ rwv,
    const float4* __restrict__ wo, float4* __restrict__ rwo)
{
    int idx = blockIdx.x * 256 + threadIdx.x;
    if (idx >= TOTAL4) return;
    const float4* src;
    float4* dst;
    int off;
    if (idx < BIG4)            { src = q;  dst = rq;  off = idx; }
    else if (idx < 2 * BIG4)   { src = k;  dst = rk;  off = idx - BIG4; }
    else if (idx < 3 * BIG4)   { src = v;  dst = rv;  off = idx - 2 * BIG4; }
    else {
        int w = idx - 3 * BIG4;
        int seg = w >> 16;
        off = w & 65535;
        switch (seg) {
            case 0: src = wq; dst = rwq; break;
            case 1: src = wk; dst = rwk; break;
            case 2: src = wv; dst = rwv; break;
            default: src = wo; dst = rwo; break;
        }
    }
    float4 x = src[off];
    x.x = tf32r(x.x); x.y = tf32r(x.y);
    x.z = tf32r(x.z); x.w = tf32r(x.w);
    dst[off] = x;
}

// ---------------------------------------------------------------------------
// GEMM (unchanged from round 6 — proven): C = A @ W^T + bias.
// Tile 128x64x32, 256 threads, cp.async double-buffered, 4-wide k-permuted
// m16n8k8 with LDS.128 fragment loads. QKV fused via blockIdx.z.
// ---------------------------------------------------------------------------
struct GemmArgs {
    const float* A;
    const float* W;
    const float* bias;
    float* C;
    int mode;
};

constexpr int GLDT = 48;
constexpr int G_ASZ = 128 * GLDT;
constexpr int G_BSZ = 64 * GLDT;
constexpr int G_STG = G_ASZ + G_BSZ;
constexpr int GEMM_SMEM = 2 * G_STG * (int)sizeof(float);   // 73728 B

__global__ __launch_bounds__(256) void gemm6(
    GemmArgs ga0, GemmArgs ga1, GemmArgs ga2)
{
    extern __shared__ __align__(16) float sm[];

    const GemmArgs& ga = (blockIdx.z == 0) ? ga0 : (blockIdx.z == 1) ? ga1 : ga2;
    const float* __restrict__ A = ga.A;
    const float* __restrict__ W = ga.W;
    const float* __restrict__ bias = ga.bias;
    float* __restrict__ C = ga.C;
    const int mode = ga.mode;

    const int tid = threadIdx.x;
    const int lane = tid & 31;
    const int warp = tid >> 5;
    const int q = lane & 3;
    const int gr = lane >> 2;
    const int m0 = blockIdx.y * 128;
    const int n0 = blockIdx.x * 64;
    const int mb = (warp >> 1) * 32;
    const int nb = (warp & 1) * 32;

    float acc[2][4][4];
#pragma unroll
    for (int i = 0; i < 2; i++)
#pragma unroll
        for (int j = 0; j < 4; j++)
#pragma unroll
            for (int e = 0; e < 4; e++) acc[i][j][e] = 0.0f;

    auto load_tiles = [&](int k0, int stage) {
        float* Ash = sm + stage * G_STG;
        float* Bsh = Ash + G_ASZ;
#pragma unroll
        for (int i = 0; i < 4; i++) {
            int lin = tid + i * 256;
            int r = lin >> 3, c4 = lin & 7;
            cp_async16(Ash + r * GLDT + c4 * 4,
                       A + (size_t)(m0 + r) * DM + k0 + c4 * 4);
        }
#pragma unroll
        for (int i = 0; i < 2; i++) {
            int lin = tid + i * 256;
            int r = lin >> 3, c4 = lin & 7;
            cp_async16(Bsh + r * GLDT + c4 * 4,
                       W + (size_t)(n0 + r) * DM + k0 + c4 * 4);
        }
        cp_async_commit();
    };

    load_tiles(0, 0);

    constexpr int NKT = DM / 32;
    for (int t = 0; t < NKT; t++) {
        float* Ash = sm + (t & 1) * G_STG;
        float* Bsh = Ash + G_ASZ;

        cp_async_wait_all();
        __syncthreads();

        if (t + 1 < NKT) load_tiles((t + 1) * 32, (t + 1) & 1);

#pragma unroll
        for (int kk = 0; kk < 2; kk++) {
            const int ko = kk * 16 + 4 * q;
            float4 alo[2], ahi[2], bb[4];
#pragma unroll
            for (int i = 0; i < 2; i++) {
                const float* ap = Ash + (mb + i * 16 + gr) * GLDT + ko;
                alo[i] = *(const float4*)ap;
                ahi[i] = *(const float4*)(ap + 8 * GLDT);
            }
#pragma unroll
            for (int j = 0; j < 4; j++)
                bb[j] = *(const float4*)(Bsh + (nb + j * 8 + gr) * GLDT + ko);
#pragma unroll
            for (int j = 0; j < 4; j++)
#pragma unroll
                for (int i = 0; i < 2; i++) {
                    mma_16n8k8(acc[i][j][0], acc[i][j][1], acc[i][j][2], acc[i][j][3],
                               __float_as_uint(alo[i].x), __float_as_uint(ahi[i].x),
                               __float_as_uint(alo[i].y), __float_as_uint(ahi[i].y),
                               __float_as_uint(bb[j].x),  __float_as_uint(bb[j].y));
                    mma_16n8k8(acc[i][j][0], acc[i][j][1], acc[i][j][2], acc[i][j][3],
                               __float_as_uint(alo[i].z), __float_as_uint(ahi[i].z),
                               __float_as_uint(alo[i].w), __float_as_uint(ahi[i].w),
                               __float_as_uint(bb[j].z),  __float_as_uint(bb[j].w));
                }
        }
        __syncthreads();
    }

    if (mode == 2) {
        const int bb2 = m0 >> 11;
        const int t0l = m0 & (TL - 1);
        const int h = n0 >> 6;
        float* ob = C + ((size_t)(bb2 * NH + h) * DH) * TL;
#pragma unroll
        for (int i = 0; i < 2; i++) {
            int t_lo = t0l + mb + i * 16 + gr;
#pragma unroll
            for (int j = 0; j < 4; j++) {
                int d = nb + j * 8 + 2 * q;
                float b0v = bias[n0 + d], b1v = bias[n0 + d + 1];
                ob[(size_t)d * TL + t_lo]           = tf32r(acc[i][j][0] + b0v);
                ob[(size_t)(d + 1) * TL + t_lo]     = tf32r(acc[i][j][1] + b1v);
                ob[(size_t)d * TL + t_lo + 8]       = tf32r(acc[i][j][2] + b0v);
                ob[(size_t)(d + 1) * TL + t_lo + 8] = tf32r(acc[i][j][3] + b1v);
            }
        }
        return;
    }

#pragma unroll
    for (int i = 0; i < 2; i++) {
        size_t row = (size_t)(m0 + mb + i * 16 + gr);
#pragma unroll
        for (int j = 0; j < 4; j++) {
            int col = n0 + nb + j * 8 + 2 * q;
            float2 bv = *(const float2*)(bias + col);
            float2 lo = make_float2(acc[i][j][0] + bv.x, acc[i][j][1] + bv.y);
            float2 hi = make_float2(acc[i][j][2] + bv.x, acc[i][j][3] + bv.y);
            if (mode == 1) {
                lo.x = tf32r(lo.x); lo.y = tf32r(lo.y);
                hi.x = tf32r(hi.x); hi.y = tf32r(hi.y);
            }
            *(float2*)(C + row * DM + col) = lo;
            *(float2*)(C + (row + 8) * DM + col) = hi;
        }
    }
}

// ---------------------------------------------------------------------------
// Flash attention v4: TWO 16-row M-strips per warp (Br=128 per 128-thr block).
// Every K/V B-fragment load feeds two mmas (strip0 + strip1); K/V smem and
// L2 traffic per mma halves. P is fed to P·V without explicit tf32 cvt
// (HMMA truncates in HW). 8 warps/SM via __launch_bounds__(128, 2).
// ---------------------------------------------------------------------------
constexpr int ALD = 72;
constexpr int TSTRIDE = 64 * ALD;
constexpr int SSTRIDE = 2 * TSTRIDE;
constexpr int ATTN_SMEM = 2 * SSTRIDE * (int)sizeof(float);  // 73728 B

__global__ __launch_bounds__(128, 2) void attn4_kernel(
    const float* __restrict__ Q, const float* __restrict__ K,
    const float* __restrict__ VT, float* __restrict__ Y)
{
    extern __shared__ __align__(16) float sm[];

    const int tid = threadIdx.x;
    const int lane = tid & 31;
    const int w = tid >> 5;
    const int q = lane & 3;
    const int gr = lane >> 2;
    const int s0 = blockIdx.x * 128;
    const int h = blockIdx.y;
    const int n = blockIdx.z;

    const float* Qg  = Q  + (size_t)n * SL * DM + (size_t)h * DH;
    const float* Kg  = K  + (size_t)n * TL * DM + (size_t)h * DH;
    const float* VTg = VT + ((size_t)(n * NH + h) * DH) * TL;
    float* Yg        = Y  + (size_t)n * SL * DM + (size_t)h * DH;

    const float SCALE = 0.125f * 1.4426950408889634f;
    // strip st covers rows s0 + st*64 + w*16 + gr (and +8)
    int r0[2];
    r0[0] = s0 + w * 16 + gr;
    r0[1] = r0[0] + 64;

    unsigned qa[2][8][4];
#pragma unroll
    for (int st = 0; st < 2; st++)
#pragma unroll
        for (int kt = 0; kt < 8; kt++) {
            int d0 = kt * 8 + 2 * q;
            float2 lo = *(const float2*)(Qg + (size_t)r0[st] * DM + d0);
            float2 hi = *(const float2*)(Qg + (size_t)(r0[st] + 8) * DM + d0);
            qa[st][kt][0] = f2tf32(lo.x * SCALE);
            qa[st][kt][1] = f2tf32(hi.x * SCALE);
            qa[st][kt][2] = f2tf32(lo.y * SCALE);
            qa[st][kt][3] = f2tf32(hi.y * SCALE);
        }

    float o[2][8][4];
#pragma unroll
    for (int st = 0; st < 2; st++)
#pragma unroll
        for (int j = 0; j < 8; j++)
#pragma unroll
            for (int e = 0; e < 4; e++) o[st][j][e] = 0.0f;

    float m_lo[2] = {-1e30f, -1e30f}, m_hi[2] = {-1e30f, -1e30f};
    float l_lo[2] = {0.0f, 0.0f},     l_hi[2] = {0.0f, 0.0f};

    auto load_chunk = [&](int t0, int stage) {
        float* Ksh = sm + stage * SSTRIDE;
        float* Vsh = Ksh + TSTRIDE;
#pragma unroll
        for (int i = 0; i < 8; i++) {
            int lin = tid + i * 128;
            int r = lin >> 4, c4 = lin & 15;
            cp_async16(Ksh + r * ALD + c4 * 4,
                       Kg + (size_t)(t0 + r) * DM + c4 * 4);
            cp_async16(Vsh + r * ALD + c4 * 4,
                       VTg + (size_t)r * TL + t0 + c4 * 4);
        }
        cp_async_commit();
    };

    load_chunk(0, 0);

    const int NCHUNK = TL / 64;
    for (int c = 0; c < NCHUNK; c++) {
        float* Ksh = sm + (c & 1) * SSTRIDE;
        float* Vsh = Ksh + TSTRIDE;

        cp_async_wait_all();
        __syncthreads();

        if (c + 1 < NCHUNK) load_chunk((c + 1) * 64, (c + 1) & 1);

        // ---- S = Q K^T : each K fragment feeds both strips ----
        float s[2][8][4];
#pragma unroll
        for (int st = 0; st < 2; st++)
#pragma unroll
            for (int j = 0; j < 8; j++)
#pragma unroll
                for (int e = 0; e < 4; e++) s[st][j][e] = 0.0f;

        const float* Kb = Ksh + gr * ALD + 2 * q;
#pragma unroll
        for (int kt = 0; kt < 8; kt++) {
#pragma unroll
            for (int j = 0; j < 8; j++) {
                float2 b = *(const float2*)(Kb + j * (8 * ALD) + kt * 8);
                unsigned b0 = __float_as_uint(b.x), b1 = __float_as_uint(b.y);
                mma_16n8k8(s[0][j][0], s[0][j][1], s[0][j][2], s[0][j][3],
                           qa[0][kt][0], qa[0][kt][1], qa[0][kt][2], qa[0][kt][3],
                           b0, b1);
                mma_16n8k8(s[1][j][0], s[1][j][1], s[1][j][2], s[1][j][3],
                           qa[1][kt][0], qa[1][kt][1], qa[1][kt][2], qa[1][kt][3],
                           b0, b1);
            }
        }

        // ---- online softmax per strip (registers + quad shuffles) ----
#pragma unroll
        for (int st = 0; st < 2; st++) {
            float mc_lo = -1e30f, mc_hi = -1e30f;
#pragma unroll
            for (int j = 0; j < 8; j++) {
                mc_lo = fmaxf(mc_lo, fmaxf(s[st][j][0], s[st][j][1]));
                mc_hi = fmaxf(mc_hi, fmaxf(s[st][j][2], s[st][j][3]));
            }
            mc_lo = fmaxf(mc_lo, __shfl_xor_sync(0xffffffffu, mc_lo, 1));
            mc_lo = fmaxf(mc_lo, __shfl_xor_sync(0xffffffffu, mc_lo, 2));
            mc_hi = fmaxf(mc_hi, __shfl_xor_sync(0xffffffffu, mc_hi, 1));
            mc_hi = fmaxf(mc_hi, __shfl_xor_sync(0xffffffffu, mc_hi, 2));

            float mn_lo = fmaxf(m_lo[st], mc_lo);
            float mn_hi = fmaxf(m_hi[st], mc_hi);
            float al = ex2f(m_lo[st] - mn_lo);
            float ah = ex2f(m_hi[st] - mn_hi);

            float sl = 0.0f, sh = 0.0f;
#pragma unroll
            for (int j = 0; j < 8; j++) {
                float p0 = ex2f(s[st][j][0] - mn_lo);
                float p1 = ex2f(s[st][j][1] - mn_lo);
                float p2 = ex2f(s[st][j][2] - mn_hi);
                float p3 = ex2f(s[st][j][3] - mn_hi);
                sl += p0 + p1;
                sh += p2 + p3;
                s[st][j][0] = p0;   // fed to HMMA as-is (HW truncates to tf32)
                s[st][j][1] = p1;
                s[st][j][2] = p2;
                s[st][j][3] = p3;
            }
            sl += __shfl_xor_sync(0xffffffffu, sl, 1);
            sl += __shfl_xor_sync(0xffffffffu, sl, 2);
            sh += __shfl_xor_sync(0xffffffffu, sh, 1);
            sh += __shfl_xor_sync(0xffffffffu, sh, 2);

            l_lo[st] = l_lo[st] * al + sl;
            l_hi[st] = l_hi[st] * ah + sh;
            m_lo[st] = mn_lo;
            m_hi[st] = mn_hi;

#pragma unroll
            for (int j = 0; j < 8; j++) {
                o[st][j][0] *= al; o[st][j][1] *= al;
                o[st][j][2] *= ah; o[st][j][3] *= ah;
            }
        }

        // ---- O += P V : each V fragment feeds both strips ----
        const float* Vb = Vsh + gr * ALD + 2 * q;
#pragma unroll
        for (int kt = 0; kt < 8; kt++) {
            unsigned a0[2], a1[2], a2[2], a3[2];
#pragma unroll
            for (int st = 0; st < 2; st++) {
                a0[st] = __float_as_uint(s[st][kt][0]);
                a1[st] = __float_as_uint(s[st][kt][2]);
                a2[st] = __float_as_uint(s[st][kt][1]);
                a3[st] = __float_as_uint(s[st][kt][3]);
            }
#pragma unroll
            for (int j = 0; j < 8; j++) {
                float2 b = *(const float2*)(Vb + j * (8 * ALD) + kt * 8);
                unsigned b0 = __float_as_uint(b.x), b1 = __float_as_uint(b.y);
                mma_16n8k8(o[0][j][0], o[0][j][1], o[0][j][2], o[0][j][3],
                           a0[0], a1[0], a2[0], a3[0], b0, b1);
                mma_16n8k8(o[1][j][0], o[1][j][1], o[1][j][2], o[1][j][3],
                           a0[1], a1[1], a2[1], a3[1], b0, b1);
            }
        }
    }

    // ---- epilogue per strip ----
#pragma unroll
    for (int st = 0; st < 2; st++) {
        float il_lo = 1.0f / l_lo[st];
        float il_hi = 1.0f / l_hi[st];
#pragma unroll
        for (int j = 0; j < 8; j++) {
            int col = 8 * j + 2 * q;
            float2 v0 = make_float2(tf32r(o[st][j][0] * il_lo), tf32r(o[st][j][1] * il_lo));
            *(float2*)(Yg + (size_t)r0[st] * DM + col) = v0;
            float2 v1 = make_float2(tf32r(o[st][j][2] * il_hi), tf32r(o[st][j][3] * il_hi));
            *(float2*)(Yg + (size_t)(r0[st] + 8) * DM + col) = v1;
        }
    }
}

// ---------------------------------------------------------------------------
// Launch
// ---------------------------------------------------------------------------
extern "C" void kernel_launch(void* const* d_in, const int* in_sizes, int n_in,
                              void* d_out, int out_size)
{
    (void)in_sizes; (void)n_in; (void)out_size;
    const float* query = (const float*)d_in[0];
    const float* key   = (const float*)d_in[1];
    const float* value = (const float*)d_in[2];
    const float* Wq = (const float*)d_in[3];
    const float* bq = (const float*)d_in[4];
    const float* Wk = (const float*)d_in[5];
    const float* bk = (const float*)d_in[6];
    const float* Wv = (const float*)d_in[7];
    const float* bv = (const float*)d_in[8];
    const float* Wo = (const float*)d_in[9];
    const float* bo = (const float*)d_in[10];
    float* out = (float*)d_out;

    float *gq, *gk, *gvt, *gy;
    float *rq, *rk, *rv, *rWq, *rWk, *rWv, *rWo;
    cudaGetSymbolAddress((void**)&gq,  g_Q);
    cudaGetSymbolAddress((void**)&gk,  g_K);
    cudaGetSymbolAddress((void**)&gvt, g_VT);
    cudaGetSymbolAddress((void**)&gy,  g_Y);
    cudaGetSymbolAddress((void**)&rq,  g_rq);
    cudaGetSymbolAddress((void**)&rk,  g_rk);
    cudaGetSymbolAddress((void**)&rv,  g_rv);
    cudaGetSymbolAddress((void**)&rWq, g_rWq);
    cudaGetSymbolAddress((void**)&rWk, g_rWk);
    cudaGetSymbolAddress((void**)&rWv, g_rWv);
    cudaGetSymbolAddress((void**)&rWo, g_rWo);

    round_all_kernel<<<(TOTAL4 + 255) / 256, 256>>>(
        (const float4*)query, (float4*)rq,
        (const float4*)key,   (float4*)rk,
        (const float4*)value, (float4*)rv,
        (const float4*)Wq, (float4*)rWq,
        (const float4*)Wk, (float4*)rWk,
        (const float4*)Wv, (float4*)rWv,
        (const float4*)Wo, (float4*)rWo);

    cudaFuncSetAttribute(gemm6, cudaFuncAttributeMaxDynamicSharedMemorySize, GEMM_SMEM);
    cudaFuncSetAttribute(attn4_kernel, cudaFuncAttributeMaxDynamicSharedMemorySize,
                         ATTN_SMEM);

    GemmArgs aq{rq, rWq, bq, gq,  0};
    GemmArgs ak{rk, rWk, bk, gk,  1};
    GemmArgs av{rv, rWv, bv, gvt, 2};
    dim3 qkvgrid(DM / 64, MROWS / 128, 3);
    gemm6<<<qkvgrid, 256, GEMM_SMEM>>>(aq, ak, av);

    dim3 agrid(SL / 128, NH, NB);            // (16, 8, 4) = 512 blocks
    attn4_kernel<<<agrid, 128, ATTN_SMEM>>>(gq, gk, gvt, gy);

    GemmArgs ao{gy, rWo, bo, out, 0};
    dim3 ogrid(DM / 64, MROWS / 128, 1);
    gemm6<<<ogrid, 256, GEMM_SMEM>>>(ao, ao, ao);
}